// round 2
// baseline (speedup 1.0000x reference)
#include <cuda_runtime.h>
#include <math.h>

// Problem constants
#define BB   4
#define NN   16384
#define CC   64
#define HH   2
#define DD   32
#define NKVC 256
#define QK_SCALE 0.17677669529663687f   // 32^-0.5

// ---------------- scratch (device globals; no allocation) ----------------
__device__ float g_wt[4096 * 64];          // conv weights transposed [k][o], 1MB
__device__ float g_part[16 * 1024 * 64];   // conv split-K partials, 4MB
__device__ float g_kbuf[8 * 256 * 32];     // K [b*2+h][m][d]
__device__ float g_vbuf[8 * 256 * 32];     // V [b*2+h][m][d]

// ---------------- kernel 0: weight transpose  w[o][c][kh][kw] -> wt[(tap*64+c)][o]
__global__ void __launch_bounds__(256) k_transpose(const float* __restrict__ srw) {
    int base = blockIdx.x * 256 + threadIdx.x;
#pragma unroll
    for (int it = 0; it < 4; it++) {
        int i = base + it * 65536;          // linear over wt: i = kg*64 + o
        int o  = i & 63;
        int kg = i >> 6;
        int c   = kg & 63;
        int tap = kg >> 6;
        int kh = tap >> 3, kw = tap & 7;
        g_wt[i] = srw[((o * 64 + c) * 8 + kh) * 8 + kw];
    }
}

// ---------------- kernel 1: SR conv as split-K implicit GEMM ----------------
// out[M=1024, O=64] partials; grid (mtile=16, ksplit=16); K-chunk 256, step 16.
__global__ void __launch_bounds__(256) k_conv(const float* __restrict__ x) {
    __shared__ float As[16][68];   // As[kk][m]
    __shared__ float Bs[16][68];   // Bs[kk][o]
    int tid = threadIdx.x;
    int mtile = blockIdx.x, ks = blockIdx.y;
    int tm = tid >> 4, to = tid & 15;
    float acc[4][4] = {};

    // per-thread load coords (A): m = tid>>2, kq = tid&3 (4 consecutive k each)
    int lm = tid >> 2, lkq = tid & 3;
    int gm = mtile * 64 + lm;
    int bb = gm >> 8, pos = gm & 255;
    int oh = pos >> 4, ow = pos & 15;
    // per-thread load coords (B): kk = tid>>4, o4 = (tid&15)*4
    int lkk = tid >> 4, lo4 = (tid & 15) * 4;

    for (int kc = 0; kc < 256; kc += 16) {
        int kg  = ks * 256 + kc + lkq * 4;      // 4 consecutive k, same tap
        int tap = kg >> 6, c = kg & 63;
        int kh = tap >> 3, kw = tap & 7;
        int pix = (oh * 8 + kh) * 128 + (ow * 8 + kw);
        float4 av = *(const float4*)&x[(bb * NN + pix) * 64 + c];
        As[lkq * 4 + 0][lm] = av.x;
        As[lkq * 4 + 1][lm] = av.y;
        As[lkq * 4 + 2][lm] = av.z;
        As[lkq * 4 + 3][lm] = av.w;
        float4 bv = *(const float4*)&g_wt[(ks * 256 + kc + lkk) * 64 + lo4];
        *(float4*)&Bs[lkk][lo4] = bv;
        __syncthreads();
#pragma unroll
        for (int kk = 0; kk < 16; kk++) {
            float4 a4 = *(float4*)&As[kk][tm * 4];
            float4 b4 = *(float4*)&Bs[kk][to * 4];
            acc[0][0] += a4.x * b4.x; acc[0][1] += a4.x * b4.y; acc[0][2] += a4.x * b4.z; acc[0][3] += a4.x * b4.w;
            acc[1][0] += a4.y * b4.x; acc[1][1] += a4.y * b4.y; acc[1][2] += a4.y * b4.z; acc[1][3] += a4.y * b4.w;
            acc[2][0] += a4.z * b4.x; acc[2][1] += a4.z * b4.y; acc[2][2] += a4.z * b4.z; acc[2][3] += a4.z * b4.w;
            acc[3][0] += a4.w * b4.x; acc[3][1] += a4.w * b4.y; acc[3][2] += a4.w * b4.z; acc[3][3] += a4.w * b4.w;
        }
        __syncthreads();
    }
    float* outp = &g_part[ks * 65536 + (mtile * 64) * 64];
#pragma unroll
    for (int i = 0; i < 4; i++)
        *(float4*)&outp[(tm * 4 + i) * 64 + to * 4] =
            make_float4(acc[i][0], acc[i][1], acc[i][2], acc[i][3]);
}

// ---------------- kernel 2: reduce partials + bias -> LN -> kv proj ----------------
__global__ void __launch_bounds__(128) k_lnkv(
    const float* __restrict__ srb, const float* __restrict__ lng,
    const float* __restrict__ lnb, const float* __restrict__ kvw,
    const float* __restrict__ kvb)
{
    __shared__ float snx[64];
    __shared__ float red[2][2];
    int m = blockIdx.x, tid = threadIdx.x;
    float v = 0.f;
    if (tid < 64) {
        v = srb[tid];
#pragma unroll
        for (int s = 0; s < 16; s++) v += g_part[s * 65536 + m * 64 + tid];
        float sv = v, sq = v * v;
#pragma unroll
        for (int off = 16; off; off >>= 1) {
            sv += __shfl_xor_sync(0xffffffffu, sv, off);
            sq += __shfl_xor_sync(0xffffffffu, sq, off);
        }
        if ((tid & 31) == 0) { red[tid >> 5][0] = sv; red[tid >> 5][1] = sq; }
    }
    __syncthreads();
    float mu  = (red[0][0] + red[1][0]) * (1.f / 64.f);
    float var = (red[0][1] + red[1][1]) * (1.f / 64.f) - mu * mu;
    float rstd = rsqrtf(var + 1e-5f);
    if (tid < 64) snx[tid] = (v - mu) * rstd * lng[tid] + lnb[tid];
    __syncthreads();

    int o = tid;                       // 0..127: 0..63 -> K, 64..127 -> V
    float acc = kvb[o];
#pragma unroll
    for (int c4 = 0; c4 < 16; c4++) {
        float4 w = *(const float4*)&kvw[o * 64 + c4 * 4];
        acc += snx[c4 * 4 + 0] * w.x + snx[c4 * 4 + 1] * w.y
             + snx[c4 * 4 + 2] * w.z + snx[c4 * 4 + 3] * w.w;
    }
    int bb = m >> 8, mm = m & 255;
    int oo = o & 63, h = oo >> 5, d = oo & 31;
    float* dst = (o < 64) ? g_kbuf : g_vbuf;
    dst[((bb * 2 + h) * 256 + mm) * 32 + d] = acc;
}

// ---------------- kernel 3: fused q-proj + QK^T + softmax + blend + @V + out-proj
// smem layout (floats):
#define SKO 0                         // K: [2][256][36]  (pad 36 -> conflict-free)
#define SVO 18432                     // V: [2][256][32]
#define SQO 34816                     // q tile: [64][68]
#define OBO 39168                     // attn-out tile: [64][68]
#define SAO 43520                     // logits/attn chunk [32][260]; aliased as x-tile
#define SWO 51840                     // weights transposed [c][o] pad 68
#define SM_FLOATS 56192               // 224768 bytes

__global__ void __launch_bounds__(256, 1) k_attn(
    const float* __restrict__ x,  const float* __restrict__ pos,
    const float* __restrict__ qw, const float* __restrict__ qb,
    const float* __restrict__ pw, const float* __restrict__ pb,
    const float* __restrict__ alpha, float* __restrict__ out)
{
    extern __shared__ float sm[];
    int tid = threadIdx.x;
    int b = blockIdx.y;
    int n0 = blockIdx.x * 64;
    float a = __ldg(alpha);

    // x tile -> SA region (64 rows x 64 ch)
#pragma unroll
    for (int it = 0; it < 4; it++) {
        int lin = it * 256 + tid;
        int r = lin >> 4, c4 = (lin & 15) * 4;
        float4 v = *(const float4*)&x[((size_t)b * NN + n0 + r) * 64 + c4];
        *(float4*)&sm[SAO + r * 68 + c4] = v;
    }
    // q_w transposed -> SW: sw[c][o]
#pragma unroll
    for (int it = 0; it < 4; it++) {
        int lin = it * 256 + tid;
        int o = lin >> 4, cq = (lin & 15) * 4;
        float4 w = *(const float4*)&qw[o * 64 + cq];
        sm[SWO + (cq + 0) * 68 + o] = w.x;
        sm[SWO + (cq + 1) * 68 + o] = w.y;
        sm[SWO + (cq + 2) * 68 + o] = w.z;
        sm[SWO + (cq + 3) * 68 + o] = w.w;
    }
    // K and V (both heads) -> smem
#pragma unroll
    for (int it = 0; it < 16; it++) {
        int lin = it * 256 + tid;            // float4 index 0..4095
        int h  = lin >> 11;
        int m  = (lin >> 3) & 255;
        int d4 = (lin & 7) * 4;
        int src = ((b * 2 + h) * 256 + m) * 32 + d4;
        *(float4*)&sm[SKO + h * 9216 + m * 36 + d4] = *(const float4*)&g_kbuf[src];
        *(float4*)&sm[SVO + h * 8192 + m * 32 + d4] = *(const float4*)&g_vbuf[src];
    }
    __syncthreads();

    // q projection (both heads), QK scale folded in
    {
        int r = tid >> 2, og = (tid & 3) * 16;
        float acc[16];
#pragma unroll
        for (int i = 0; i < 16; i++) acc[i] = qb[og + i];
        for (int c = 0; c < 64; c++) {
            float xv = sm[SAO + r * 68 + c];
#pragma unroll
            for (int i4 = 0; i4 < 4; i4++) {
                float4 w4 = *(float4*)&sm[SWO + c * 68 + og + i4 * 4];
                acc[i4 * 4 + 0] += xv * w4.x; acc[i4 * 4 + 1] += xv * w4.y;
                acc[i4 * 4 + 2] += xv * w4.z; acc[i4 * 4 + 3] += xv * w4.w;
            }
        }
#pragma unroll
        for (int i = 0; i < 16; i++) sm[SQO + r * 68 + og + i] = acc[i] * QK_SCALE;
    }
    __syncthreads();

    // proj_w transposed -> SW (only read at the end, after syncs)
#pragma unroll
    for (int it = 0; it < 4; it++) {
        int lin = it * 256 + tid;
        int o = lin >> 4, cq = (lin & 15) * 4;
        float4 w = *(const float4*)&pw[o * 64 + cq];
        sm[SWO + (cq + 0) * 68 + o] = w.x;
        sm[SWO + (cq + 1) * 68 + o] = w.y;
        sm[SWO + (cq + 2) * 68 + o] = w.z;
        sm[SWO + (cq + 3) * 68 + o] = w.w;
    }

    for (int h = 0; h < 2; h++) {
        for (int ch = 0; ch < 2; ch++) {
            int r0 = ch * 32;
            // ---- logits: 32 rows x 256 keys
            {
                int r = tid >> 3, kq = tid & 7;
                float qr[32];
#pragma unroll
                for (int d4 = 0; d4 < 8; d4++) {
                    float4 q4 = *(float4*)&sm[SQO + (r0 + r) * 68 + h * 32 + d4 * 4];
                    qr[d4 * 4 + 0] = q4.x; qr[d4 * 4 + 1] = q4.y;
                    qr[d4 * 4 + 2] = q4.z; qr[d4 * 4 + 3] = q4.w;
                }
#pragma unroll 2
                for (int j = 0; j < 32; j++) {
                    int m = kq + j * 8;
                    float s0 = 0.f, s1 = 0.f, s2 = 0.f, s3 = 0.f;
#pragma unroll
                    for (int d4 = 0; d4 < 8; d4++) {
                        float4 k4 = *(float4*)&sm[SKO + h * 9216 + m * 36 + d4 * 4];
                        s0 += qr[d4 * 4 + 0] * k4.x; s1 += qr[d4 * 4 + 1] * k4.y;
                        s2 += qr[d4 * 4 + 2] * k4.z; s3 += qr[d4 * 4 + 3] * k4.w;
                    }
                    sm[SAO + r * 260 + m] = (s0 + s1) + (s2 + s3);
                }
            }
            __syncthreads();
            // ---- softmax + positional blend (warp w handles 4 rows)
            {
                int w = tid >> 5, lane = tid & 31;
#pragma unroll
                for (int rr = 0; rr < 4; rr++) {
                    int lr = w * 4 + rr;
                    float* row = &sm[SAO + lr * 260];
                    float vals[8];
                    float mx = -1e30f;
#pragma unroll
                    for (int jj = 0; jj < 8; jj++) {
                        vals[jj] = row[lane + jj * 32];
                        mx = fmaxf(mx, vals[jj]);
                    }
#pragma unroll
                    for (int off = 16; off; off >>= 1)
                        mx = fmaxf(mx, __shfl_xor_sync(0xffffffffu, mx, off));
                    float s = 0.f;
#pragma unroll
                    for (int jj = 0; jj < 8; jj++) { vals[jj] = __expf(vals[jj] - mx); s += vals[jj]; }
#pragma unroll
                    for (int off = 16; off; off >>= 1)
                        s += __shfl_xor_sync(0xffffffffu, s, off);
                    float inv = (1.f - a) / s;
                    const float* prow = &pos[(((size_t)(b * 2 + h)) * NN + n0 + r0 + lr) * 256];
#pragma unroll
                    for (int jj = 0; jj < 8; jj++)
                        row[lane + jj * 32] = vals[jj] * inv + a * __ldg(&prow[lane + jj * 32]);
                }
            }
            __syncthreads();
            // ---- attn @ V
            {
                int r = tid >> 3, dg = (tid & 7) * 4;
                float o0 = 0.f, o1 = 0.f, o2 = 0.f, o3 = 0.f;
#pragma unroll 4
                for (int m = 0; m < 256; m++) {
                    float av = sm[SAO + r * 260 + m];
                    float4 v4 = *(float4*)&sm[SVO + h * 8192 + m * 32 + dg];
                    o0 += av * v4.x; o1 += av * v4.y; o2 += av * v4.z; o3 += av * v4.w;
                }
                *(float4*)&sm[OBO + (r0 + r) * 68 + h * 32 + dg] = make_float4(o0, o1, o2, o3);
            }
            __syncthreads();
        }
    }
    // ---- output projection
    {
        int r = tid >> 2, og = (tid & 3) * 16;
        float acc[16];
#pragma unroll
        for (int i = 0; i < 16; i++) acc[i] = pb[og + i];
        for (int c = 0; c < 64; c++) {
            float xv = sm[OBO + r * 68 + c];
#pragma unroll
            for (int i4 = 0; i4 < 4; i4++) {
                float4 w4 = *(float4*)&sm[SWO + c * 68 + og + i4 * 4];
                acc[i4 * 4 + 0] += xv * w4.x; acc[i4 * 4 + 1] += xv * w4.y;
                acc[i4 * 4 + 2] += xv * w4.z; acc[i4 * 4 + 3] += xv * w4.w;
            }
        }
        float* op = &out[((size_t)b * NN + n0 + r) * 64 + og];
#pragma unroll
        for (int i4 = 0; i4 < 4; i4++)
            *(float4*)&op[i4 * 4] =
                make_float4(acc[i4 * 4], acc[i4 * 4 + 1], acc[i4 * 4 + 2], acc[i4 * 4 + 3]);
    }
}

// ---------------- launch ----------------
extern "C" void kernel_launch(void* const* d_in, const int* in_sizes, int n_in,
                              void* d_out, int out_size) {
    const float* x     = (const float*)d_in[0];
    const float* pos   = (const float*)d_in[1];
    const float* qw    = (const float*)d_in[2];
    const float* qb    = (const float*)d_in[3];
    const float* kvw   = (const float*)d_in[4];
    const float* kvb   = (const float*)d_in[5];
    const float* pw    = (const float*)d_in[6];
    const float* pb    = (const float*)d_in[7];
    const float* srw   = (const float*)d_in[8];
    const float* srb   = (const float*)d_in[9];
    const float* lng   = (const float*)d_in[10];
    const float* lnb   = (const float*)d_in[11];
    const float* alpha = (const float*)d_in[12];
    float* out = (float*)d_out;

    cudaFuncSetAttribute(k_attn, cudaFuncAttributeMaxDynamicSharedMemorySize,
                         SM_FLOATS * 4);

    k_transpose<<<256, 256>>>(srw);
    k_conv<<<dim3(16, 16), 256>>>(x);
    k_lnkv<<<1024, 128>>>(srb, lng, lnb, kvw, kvb);
    k_attn<<<dim3(256, 4), 256, SM_FLOATS * 4>>>(x, pos, qw, qb, pw, pb, alpha, out);
}

// round 3
// speedup vs baseline: 2.6928x; 2.6928x over previous
#include <cuda_runtime.h>
#include <math.h>

// Problem constants
#define BB   4
#define NN   16384
#define CC   64
#define HH   2
#define DD   32
#define NKVC 256
#define QK_SCALE 0.17677669529663687f   // 32^-0.5

// ---------------- scratch (device globals; no allocation) ----------------
__device__ float g_wt[4096 * 64];          // conv weights transposed [k][o], 1MB
__device__ float g_part[16 * 1024 * 64];   // conv split-K partials, 4MB
__device__ float g_kbuf[8 * 256 * 32];     // K [b*2+h][m][d]
__device__ float g_vbuf[8 * 256 * 32];     // V [b*2+h][m][d]

// ---------------- tf32 mma helpers ----------------
__device__ __forceinline__ unsigned f2tf(float f) {
    unsigned u; asm("cvt.rna.tf32.f32 %0, %1;" : "=r"(u) : "f"(f)); return u;
}
__device__ __forceinline__ void mma8(float d[4], const unsigned a[4], const unsigned b[2]) {
    asm volatile(
        "mma.sync.aligned.m16n8k8.row.col.f32.tf32.tf32.f32 "
        "{%0,%1,%2,%3},{%4,%5,%6,%7},{%8,%9},{%0,%1,%2,%3};"
        : "+f"(d[0]), "+f"(d[1]), "+f"(d[2]), "+f"(d[3])
        : "r"(a[0]), "r"(a[1]), "r"(a[2]), "r"(a[3]), "r"(b[0]), "r"(b[1]));
}

// ---------------- kernel 0: weight transpose  w[o][c][kh][kw] -> wt[(tap*64+c)][o]
__global__ void __launch_bounds__(256) k_transpose(const float* __restrict__ srw) {
    int base = blockIdx.x * 256 + threadIdx.x;
#pragma unroll
    for (int it = 0; it < 4; it++) {
        int i = base + it * 65536;
        int o  = i & 63;
        int kg = i >> 6;
        int c   = kg & 63;
        int tap = kg >> 6;
        int kh = tap >> 3, kw = tap & 7;
        g_wt[i] = srw[((o * 64 + c) * 8 + kh) * 8 + kw];
    }
}

// ---------------- kernel 1: SR conv as split-K implicit GEMM ----------------
__global__ void __launch_bounds__(256) k_conv(const float* __restrict__ x) {
    __shared__ float As[16][68];
    __shared__ float Bs[16][68];
    int tid = threadIdx.x;
    int mtile = blockIdx.x, ks = blockIdx.y;
    int tm = tid >> 4, to = tid & 15;
    float acc[4][4] = {};

    int lm = tid >> 2, lkq = tid & 3;
    int gm = mtile * 64 + lm;
    int bb = gm >> 8, pos = gm & 255;
    int oh = pos >> 4, ow = pos & 15;
    int lkk = tid >> 4, lo4 = (tid & 15) * 4;

    for (int kc = 0; kc < 256; kc += 16) {
        int kg  = ks * 256 + kc + lkq * 4;
        int tap = kg >> 6, c = kg & 63;
        int kh = tap >> 3, kw = tap & 7;
        int pix = (oh * 8 + kh) * 128 + (ow * 8 + kw);
        float4 av = *(const float4*)&x[(bb * NN + pix) * 64 + c];
        As[lkq * 4 + 0][lm] = av.x;
        As[lkq * 4 + 1][lm] = av.y;
        As[lkq * 4 + 2][lm] = av.z;
        As[lkq * 4 + 3][lm] = av.w;
        float4 bv = *(const float4*)&g_wt[(ks * 256 + kc + lkk) * 64 + lo4];
        *(float4*)&Bs[lkk][lo4] = bv;
        __syncthreads();
#pragma unroll
        for (int kk = 0; kk < 16; kk++) {
            float4 a4 = *(float4*)&As[kk][tm * 4];
            float4 b4 = *(float4*)&Bs[kk][to * 4];
            acc[0][0] += a4.x * b4.x; acc[0][1] += a4.x * b4.y; acc[0][2] += a4.x * b4.z; acc[0][3] += a4.x * b4.w;
            acc[1][0] += a4.y * b4.x; acc[1][1] += a4.y * b4.y; acc[1][2] += a4.y * b4.z; acc[1][3] += a4.y * b4.w;
            acc[2][0] += a4.z * b4.x; acc[2][1] += a4.z * b4.y; acc[2][2] += a4.z * b4.z; acc[2][3] += a4.z * b4.w;
            acc[3][0] += a4.w * b4.x; acc[3][1] += a4.w * b4.y; acc[3][2] += a4.w * b4.z; acc[3][3] += a4.w * b4.w;
        }
        __syncthreads();
    }
    float* outp = &g_part[ks * 65536 + (mtile * 64) * 64];
#pragma unroll
    for (int i = 0; i < 4; i++)
        *(float4*)&outp[(tm * 4 + i) * 64 + to * 4] =
            make_float4(acc[i][0], acc[i][1], acc[i][2], acc[i][3]);
}

// ---------------- kernel 2: reduce partials + bias -> LN -> kv proj ----------------
__global__ void __launch_bounds__(128) k_lnkv(
    const float* __restrict__ srb, const float* __restrict__ lng,
    const float* __restrict__ lnb, const float* __restrict__ kvw,
    const float* __restrict__ kvb)
{
    __shared__ float snx[64];
    __shared__ float red[2][2];
    int m = blockIdx.x, tid = threadIdx.x;
    float v = 0.f;
    if (tid < 64) {
        v = srb[tid];
#pragma unroll
        for (int s = 0; s < 16; s++) v += g_part[s * 65536 + m * 64 + tid];
        float sv = v, sq = v * v;
#pragma unroll
        for (int off = 16; off; off >>= 1) {
            sv += __shfl_xor_sync(0xffffffffu, sv, off);
            sq += __shfl_xor_sync(0xffffffffu, sq, off);
        }
        if ((tid & 31) == 0) { red[tid >> 5][0] = sv; red[tid >> 5][1] = sq; }
    }
    __syncthreads();
    float mu  = (red[0][0] + red[1][0]) * (1.f / 64.f);
    float var = (red[0][1] + red[1][1]) * (1.f / 64.f) - mu * mu;
    float rstd = rsqrtf(var + 1e-5f);
    if (tid < 64) snx[tid] = (v - mu) * rstd * lng[tid] + lnb[tid];
    __syncthreads();

    int o = tid;
    float acc = kvb[o];
#pragma unroll
    for (int c4 = 0; c4 < 16; c4++) {
        float4 w = *(const float4*)&kvw[o * 64 + c4 * 4];
        acc += snx[c4 * 4 + 0] * w.x + snx[c4 * 4 + 1] * w.y
             + snx[c4 * 4 + 2] * w.z + snx[c4 * 4 + 3] * w.w;
    }
    int bb = m >> 8, mm = m & 255;
    int oo = o & 63, h = oo >> 5, d = oo & 31;
    float* dst = (o < 64) ? g_kbuf : g_vbuf;
    dst[((bb * 2 + h) * 256 + mm) * 32 + d] = acc;
}

// ---------------- kernel 3: fused attention with tf32 mma.sync ----------------
// smem layout (floats):
#define SW  0       // weights [o*68+c] (qw then pw)
#define SQ  4352    // q [r*68 + h*32+d], scale folded
#define SOB 8704    // attn-out [r*68 + h*32+d]
#define SK  13056   // K current head [m*36+d]
#define SV  22272   // V current head [m*36+d]
#define SA  31488   // x-tile [r*68+c] initially; logits [r*260+m]; out staging
#define SMF 48128   // 192512 bytes

__global__ void __launch_bounds__(256, 1) k_attn(
    const float* __restrict__ x,  const float* __restrict__ pos,
    const float* __restrict__ qw, const float* __restrict__ qb,
    const float* __restrict__ pw, const float* __restrict__ pb,
    const float* __restrict__ alpha, float* __restrict__ out)
{
    extern __shared__ float sm[];
    int tid = threadIdx.x, w = tid >> 5, ln = tid & 31;
    int lr = ln >> 2, lc = ln & 3;       // fragment row/col within warp
    int b = blockIdx.y;
    int n0 = blockIdx.x * 64;
    float a_ = __ldg(alpha);

    // load x tile -> SA [r*68+c], qw -> SW [o*68+c]
#pragma unroll
    for (int it = 0; it < 4; it++) {
        int lin = it * 256 + tid;
        int r = lin >> 4, c4 = (lin & 15) * 4;
        *(float4*)&sm[SA + r * 68 + c4] = *(const float4*)&x[((size_t)b * NN + n0 + r) * 64 + c4];
        *(float4*)&sm[SW + r * 68 + c4] = *(const float4*)&qw[r * 64 + c4];
    }
    __syncthreads();

    // ---- q-proj: D[64,64] = x[64,64] @ qw^T ----
    {
        int mt = w >> 1, nh = w & 1;
        float acc[4][4] = {};
#pragma unroll
        for (int ks = 0; ks < 8; ks++) {
            int kb = ks * 8;
            const float* ab = &sm[SA + (mt * 16 + lr) * 68 + kb + lc];
            unsigned af[4] = {f2tf(ab[0]), f2tf(ab[8 * 68]), f2tf(ab[4]), f2tf(ab[8 * 68 + 4])};
#pragma unroll
            for (int nt = 0; nt < 4; nt++) {
                int nb = nh * 32 + nt * 8;
                const float* bb = &sm[SW + (nb + lr) * 68 + kb + lc];
                unsigned bf[2] = {f2tf(bb[0]), f2tf(bb[4])};
                mma8(acc[nt], af, bf);
            }
        }
#pragma unroll
        for (int nt = 0; nt < 4; nt++) {
            int nb = nh * 32 + nt * 8;
            int r = mt * 16 + lr, c0 = nb + 2 * lc;
            float b0 = __ldg(&qb[c0]), b1 = __ldg(&qb[c0 + 1]);
            sm[SQ + r * 68 + c0]           = (acc[nt][0] + b0) * QK_SCALE;
            sm[SQ + r * 68 + c0 + 1]       = (acc[nt][1] + b1) * QK_SCALE;
            sm[SQ + (r + 8) * 68 + c0]     = (acc[nt][2] + b0) * QK_SCALE;
            sm[SQ + (r + 8) * 68 + c0 + 1] = (acc[nt][3] + b1) * QK_SCALE;
        }
    }
    __syncthreads();
    // pw -> SW (q-proj reads done)
#pragma unroll
    for (int it = 0; it < 4; it++) {
        int lin = it * 256 + tid;
        int r = lin >> 4, c4 = (lin & 15) * 4;
        *(float4*)&sm[SW + r * 68 + c4] = *(const float4*)&pw[r * 64 + c4];
    }

    for (int h = 0; h < 2; h++) {
        __syncthreads();   // protect SK/SV/SA rewrite vs previous consumers
        // load K/V head -> smem (pad 36)
#pragma unroll
        for (int it = 0; it < 8; it++) {
            int lin = it * 256 + tid;           // 2048 float4
            int m = lin >> 3, d4 = (lin & 7) * 4;
            int src = ((b * 2 + h) * 256 + m) * 32 + d4;
            *(float4*)&sm[SK + m * 36 + d4] = *(const float4*)&g_kbuf[src];
            *(float4*)&sm[SV + m * 36 + d4] = *(const float4*)&g_vbuf[src];
        }
        __syncthreads();

        // ---- logits: S[64,256] = q_h[64,32] @ K_h^T ----
        {
            int mt = w & 3, nh = w >> 2;
            float acc[16][4];
#pragma unroll
            for (int i = 0; i < 16; i++)
                acc[i][0] = acc[i][1] = acc[i][2] = acc[i][3] = 0.f;
#pragma unroll
            for (int ks = 0; ks < 4; ks++) {
                int kb = ks * 8;
                const float* ab = &sm[SQ + (mt * 16 + lr) * 68 + h * 32 + kb + lc];
                unsigned af[4] = {f2tf(ab[0]), f2tf(ab[8 * 68]), f2tf(ab[4]), f2tf(ab[8 * 68 + 4])};
#pragma unroll
                for (int nt = 0; nt < 16; nt++) {
                    int nb = nh * 128 + nt * 8;
                    const float* bb = &sm[SK + (nb + lr) * 36 + kb + lc];
                    unsigned bf[2] = {f2tf(bb[0]), f2tf(bb[4])};
                    mma8(acc[nt], af, bf);
                }
            }
#pragma unroll
            for (int nt = 0; nt < 16; nt++) {
                int nb = nh * 128 + nt * 8;
                int r = mt * 16 + lr, c0 = nb + 2 * lc;
                sm[SA + r * 260 + c0]           = acc[nt][0];
                sm[SA + r * 260 + c0 + 1]       = acc[nt][1];
                sm[SA + (r + 8) * 260 + c0]     = acc[nt][2];
                sm[SA + (r + 8) * 260 + c0 + 1] = acc[nt][3];
            }
        }
        __syncthreads();

        // ---- softmax + positional blend (warp w: rows w*8..w*8+7) ----
#pragma unroll
        for (int rr = 0; rr < 8; rr++) {
            int r = w * 8 + rr;
            float* row = &sm[SA + r * 260];
            float vals[8];
            float mx = -1e30f;
#pragma unroll
            for (int jj = 0; jj < 8; jj++) {
                vals[jj] = row[ln + jj * 32];
                mx = fmaxf(mx, vals[jj]);
            }
#pragma unroll
            for (int off = 16; off; off >>= 1)
                mx = fmaxf(mx, __shfl_xor_sync(0xffffffffu, mx, off));
            float s = 0.f;
#pragma unroll
            for (int jj = 0; jj < 8; jj++) { vals[jj] = __expf(vals[jj] - mx); s += vals[jj]; }
#pragma unroll
            for (int off = 16; off; off >>= 1)
                s += __shfl_xor_sync(0xffffffffu, s, off);
            float inv = (1.f - a_) / s;
            const float* prow = &pos[(((size_t)(b * 2 + h)) * NN + n0 + r) * 256];
#pragma unroll
            for (int jj = 0; jj < 8; jj++)
                row[ln + jj * 32] = vals[jj] * inv + a_ * __ldg(&prow[ln + jj * 32]);
        }
        __syncthreads();

        // ---- attn @ V: O[64,32] = attn[64,256] @ V[256,32] ----
        {
            int mt = w >> 1, ntp = w & 1;
            float acc[2][4] = {};
#pragma unroll 4
            for (int ks = 0; ks < 32; ks++) {
                int kb = ks * 8;
                const float* ab = &sm[SA + (mt * 16 + lr) * 260 + kb + lc];
                unsigned af[4] = {f2tf(ab[0]), f2tf(ab[8 * 260]), f2tf(ab[4]), f2tf(ab[8 * 260 + 4])};
#pragma unroll
                for (int nt = 0; nt < 2; nt++) {
                    int nb = ntp * 16 + nt * 8;
                    const float* bb = &sm[SV + (kb + lc) * 36 + nb + lr];
                    unsigned bf[2] = {f2tf(bb[0]), f2tf(bb[4 * 36])};
                    mma8(acc[nt], af, bf);
                }
            }
#pragma unroll
            for (int nt = 0; nt < 2; nt++) {
                int nb = ntp * 16 + nt * 8;
                int r = mt * 16 + lr, c0 = h * 32 + nb + 2 * lc;
                sm[SOB + r * 68 + c0]           = acc[nt][0];
                sm[SOB + r * 68 + c0 + 1]       = acc[nt][1];
                sm[SOB + (r + 8) * 68 + c0]     = acc[nt][2];
                sm[SOB + (r + 8) * 68 + c0 + 1] = acc[nt][3];
            }
        }
    }
    __syncthreads();

    // ---- out-proj: D[64,64] = ob[64,64] @ pw^T + pb ----
    {
        int mt = w >> 1, nh = w & 1;
        float acc[4][4] = {};
#pragma unroll
        for (int ks = 0; ks < 8; ks++) {
            int kb = ks * 8;
            const float* ab = &sm[SOB + (mt * 16 + lr) * 68 + kb + lc];
            unsigned af[4] = {f2tf(ab[0]), f2tf(ab[8 * 68]), f2tf(ab[4]), f2tf(ab[8 * 68 + 4])};
#pragma unroll
            for (int nt = 0; nt < 4; nt++) {
                int nb = nh * 32 + nt * 8;
                const float* bb = &sm[SW + (nb + lr) * 68 + kb + lc];
                unsigned bf[2] = {f2tf(bb[0]), f2tf(bb[4])};
                mma8(acc[nt], af, bf);
            }
        }
#pragma unroll
        for (int nt = 0; nt < 4; nt++) {
            int nb = nh * 32 + nt * 8;
            int r = mt * 16 + lr, c0 = nb + 2 * lc;
            float b0 = __ldg(&pb[c0]), b1 = __ldg(&pb[c0 + 1]);
            sm[SA + r * 68 + c0]           = acc[nt][0] + b0;
            sm[SA + r * 68 + c0 + 1]       = acc[nt][1] + b1;
            sm[SA + (r + 8) * 68 + c0]     = acc[nt][2] + b0;
            sm[SA + (r + 8) * 68 + c0 + 1] = acc[nt][3] + b1;
        }
    }
    __syncthreads();
#pragma unroll
    for (int it = 0; it < 4; it++) {
        int lin = it * 256 + tid;
        int r = lin >> 4, c4 = (lin & 15) * 4;
        *(float4*)&out[((size_t)b * NN + n0 + r) * 64 + c4] = *(float4*)&sm[SA + r * 68 + c4];
    }
}

// ---------------- launch ----------------
extern "C" void kernel_launch(void* const* d_in, const int* in_sizes, int n_in,
                              void* d_out, int out_size) {
    const float* x     = (const float*)d_in[0];
    const float* pos   = (const float*)d_in[1];
    const float* qw    = (const float*)d_in[2];
    const float* qb    = (const float*)d_in[3];
    const float* kvw   = (const float*)d_in[4];
    const float* kvb   = (const float*)d_in[5];
    const float* pw    = (const float*)d_in[6];
    const float* pb    = (const float*)d_in[7];
    const float* srw   = (const float*)d_in[8];
    const float* srb   = (const float*)d_in[9];
    const float* lng   = (const float*)d_in[10];
    const float* lnb   = (const float*)d_in[11];
    const float* alpha = (const float*)d_in[12];
    float* out = (float*)d_out;

    cudaFuncSetAttribute(k_attn, cudaFuncAttributeMaxDynamicSharedMemorySize,
                         SMF * 4);

    k_transpose<<<256, 256>>>(srw);
    k_conv<<<dim3(16, 16), 256>>>(x);
    k_lnkv<<<1024, 128>>>(srb, lng, lnb, kvw, kvb);
    k_attn<<<dim3(256, 4), 256, SMF * 4>>>(x, pos, qw, qb, pw, pb, alpha, out);
}

// round 5
// speedup vs baseline: 3.3344x; 1.2383x over previous
#include <cuda_runtime.h>
#include <math.h>

// Problem constants
#define BB   4
#define NN   16384
#define CC   64
#define HH   2
#define DD   32
#define NKVC 256
#define QK_SCALE 0.17677669529663687f   // 32^-0.5

// ---------------- scratch (device globals; no allocation) ----------------
__device__ float g_wt[4096 * 64];          // conv weights transposed [k][o], 1MB
__device__ float g_part[16 * 1024 * 64];   // conv split-K partials, 4MB
__device__ float g_kbuf[8 * 256 * 32];     // K [b*2+h][m][d]
__device__ float g_vbuf[8 * 256 * 32];     // V [b*2+h][m][d]

// ---------------- tf32 mma helpers ----------------
__device__ __forceinline__ unsigned f2tf(float f) {
    unsigned u; asm("cvt.rna.tf32.f32 %0, %1;" : "=r"(u) : "f"(f)); return u;
}
__device__ __forceinline__ uint4 f2tf4(float4 v) {
    return make_uint4(f2tf(v.x), f2tf(v.y), f2tf(v.z), f2tf(v.w));
}
__device__ __forceinline__ void mma8(float d[4], const unsigned a[4], const unsigned b[2]) {
    asm volatile(
        "mma.sync.aligned.m16n8k8.row.col.f32.tf32.tf32.f32 "
        "{%0,%1,%2,%3},{%4,%5,%6,%7},{%8,%9},{%0,%1,%2,%3};"
        : "+f"(d[0]), "+f"(d[1]), "+f"(d[2]), "+f"(d[3])
        : "r"(a[0]), "r"(a[1]), "r"(a[2]), "r"(a[3]), "r"(b[0]), "r"(b[1]));
}

// ---------------- kernel 0: weight transpose ----------------
__global__ void __launch_bounds__(256) k_transpose(const float* __restrict__ srw) {
    int base = blockIdx.x * 256 + threadIdx.x;
#pragma unroll
    for (int it = 0; it < 4; it++) {
        int i = base + it * 65536;
        int o  = i & 63;
        int kg = i >> 6;
        int c   = kg & 63;
        int tap = kg >> 6;
        int kh = tap >> 3, kw = tap & 7;
        g_wt[i] = srw[((o * 64 + c) * 8 + kh) * 8 + kw];
    }
}

// ---------------- kernel 1: SR conv as split-K implicit GEMM ----------------
__global__ void __launch_bounds__(256) k_conv(const float* __restrict__ x) {
    __shared__ float As[16][68];
    __shared__ float Bs[16][68];
    int tid = threadIdx.x;
    int mtile = blockIdx.x, ks = blockIdx.y;
    int tm = tid >> 4, to = tid & 15;
    float acc[4][4] = {};

    int lm = tid >> 2, lkq = tid & 3;
    int gm = mtile * 64 + lm;
    int bb = gm >> 8, pos = gm & 255;
    int oh = pos >> 4, ow = pos & 15;
    int lkk = tid >> 4, lo4 = (tid & 15) * 4;

    for (int kc = 0; kc < 256; kc += 16) {
        int kg  = ks * 256 + kc + lkq * 4;
        int tap = kg >> 6, c = kg & 63;
        int kh = tap >> 3, kw = tap & 7;
        int pix = (oh * 8 + kh) * 128 + (ow * 8 + kw);
        float4 av = *(const float4*)&x[(bb * NN + pix) * 64 + c];
        As[lkq * 4 + 0][lm] = av.x;
        As[lkq * 4 + 1][lm] = av.y;
        As[lkq * 4 + 2][lm] = av.z;
        As[lkq * 4 + 3][lm] = av.w;
        float4 bv = *(const float4*)&g_wt[(ks * 256 + kc + lkk) * 64 + lo4];
        *(float4*)&Bs[lkk][lo4] = bv;
        __syncthreads();
#pragma unroll
        for (int kk = 0; kk < 16; kk++) {
            float4 a4 = *(float4*)&As[kk][tm * 4];
            float4 b4 = *(float4*)&Bs[kk][to * 4];
            acc[0][0] += a4.x * b4.x; acc[0][1] += a4.x * b4.y; acc[0][2] += a4.x * b4.z; acc[0][3] += a4.x * b4.w;
            acc[1][0] += a4.y * b4.x; acc[1][1] += a4.y * b4.y; acc[1][2] += a4.y * b4.z; acc[1][3] += a4.y * b4.w;
            acc[2][0] += a4.z * b4.x; acc[2][1] += a4.z * b4.y; acc[2][2] += a4.z * b4.z; acc[2][3] += a4.z * b4.w;
            acc[3][0] += a4.w * b4.x; acc[3][1] += a4.w * b4.y; acc[3][2] += a4.w * b4.z; acc[3][3] += a4.w * b4.w;
        }
        __syncthreads();
    }
    float* outp = &g_part[ks * 65536 + (mtile * 64) * 64];
#pragma unroll
    for (int i = 0; i < 4; i++)
        *(float4*)&outp[(tm * 4 + i) * 64 + to * 4] =
            make_float4(acc[i][0], acc[i][1], acc[i][2], acc[i][3]);
}

// ---------------- kernel 2: reduce partials + bias -> LN -> kv proj ----------------
__global__ void __launch_bounds__(128) k_lnkv(
    const float* __restrict__ srb, const float* __restrict__ lng,
    const float* __restrict__ lnb, const float* __restrict__ kvw,
    const float* __restrict__ kvb)
{
    __shared__ float snx[64];
    __shared__ float red[2][2];
    int m = blockIdx.x, tid = threadIdx.x;
    float v = 0.f;
    if (tid < 64) {
        v = srb[tid];
#pragma unroll
        for (int s = 0; s < 16; s++) v += g_part[s * 65536 + m * 64 + tid];
        float sv = v, sq = v * v;
#pragma unroll
        for (int off = 16; off; off >>= 1) {
            sv += __shfl_xor_sync(0xffffffffu, sv, off);
            sq += __shfl_xor_sync(0xffffffffu, sq, off);
        }
        if ((tid & 31) == 0) { red[tid >> 5][0] = sv; red[tid >> 5][1] = sq; }
    }
    __syncthreads();
    float mu  = (red[0][0] + red[1][0]) * (1.f / 64.f);
    float var = (red[0][1] + red[1][1]) * (1.f / 64.f) - mu * mu;
    float rstd = rsqrtf(var + 1e-5f);
    if (tid < 64) snx[tid] = (v - mu) * rstd * lng[tid] + lnb[tid];
    __syncthreads();

    int o = tid;
    float acc = kvb[o];
#pragma unroll
    for (int c4 = 0; c4 < 16; c4++) {
        float4 w = *(const float4*)&kvw[o * 64 + c4 * 4];
        acc += snx[c4 * 4 + 0] * w.x + snx[c4 * 4 + 1] * w.y
             + snx[c4 * 4 + 2] * w.z + snx[c4 * 4 + 3] * w.w;
    }
    int bb = m >> 8, mm = m & 255;
    int oo = o & 63, h = oo >> 5, d = oo & 31;
    float* dst = (o < 64) ? g_kbuf : g_vbuf;
    dst[((bb * 2 + h) * 256 + mm) * 32 + d] = acc;
}

// ---------------- kernel 3: fused attention, tf32 mma, 512 threads ----------------
// smem layout (4-byte words):
#define SW  0       // weights tf32 [o*68+c]
#define SQ  4352    // q tf32 [r*68 + h*32+d], scale folded
#define SOB 8704    // attn-out tf32 [r*68 + h*32+d]
#define SK  13056   // K tf32 current head [m*36+d]
#define SV  22272   // V tf32 current head [m*40+d]   (stride 40: conflict-free MN reads)
#define SA  32512   // x-tile tf32 [r*68+c]; logits f32 / attn tf32 [r*260+m]; out f32
#define SMF 49152   // 196608 bytes

__global__ void __launch_bounds__(512, 1) k_attn(
    const float* __restrict__ x,  const float* __restrict__ pos,
    const float* __restrict__ qw, const float* __restrict__ qb,
    const float* __restrict__ pw, const float* __restrict__ pb,
    const float* __restrict__ alpha, float* __restrict__ out)
{
    extern __shared__ float sm[];
    unsigned* smU = (unsigned*)sm;
    int tid = threadIdx.x, w = tid >> 5, ln = tid & 31;
    int lr = ln >> 2, lc = ln & 3;
    int b = blockIdx.y;
    int n0 = blockIdx.x * 64;
    float a_ = __ldg(alpha);

    // x tile -> SA (tf32), qw -> SW (tf32)
#pragma unroll
    for (int it = 0; it < 2; it++) {
        int lin = it * 512 + tid;              // 0..1023
        int r = lin >> 4, c4 = (lin & 15) * 4;
        *(uint4*)&smU[SA + r * 68 + c4] =
            f2tf4(*(const float4*)&x[((size_t)b * NN + n0 + r) * 64 + c4]);
        *(uint4*)&smU[SW + r * 68 + c4] =
            f2tf4(*(const float4*)&qw[r * 64 + c4]);
    }
    __syncthreads();

    // ---- q-proj: D[64,64] = x @ qw^T ----
    {
        int mt = w >> 2, nq = w & 3;
        float acc[2][4] = {};
#pragma unroll
        for (int ks = 0; ks < 8; ks++) {
            int kb = ks * 8;
            const unsigned* ab = &smU[SA + (mt * 16 + lr) * 68 + kb + lc];
            unsigned af[4] = {ab[0], ab[8 * 68], ab[4], ab[8 * 68 + 4]};
#pragma unroll
            for (int nt = 0; nt < 2; nt++) {
                int nb = nq * 16 + nt * 8;
                const unsigned* bb = &smU[SW + (nb + lr) * 68 + kb + lc];
                unsigned bf[2] = {bb[0], bb[4]};
                mma8(acc[nt], af, bf);
            }
        }
#pragma unroll
        for (int nt = 0; nt < 2; nt++) {
            int nb = nq * 16 + nt * 8;
            int r = mt * 16 + lr, c0 = nb + 2 * lc;
            float b0 = __ldg(&qb[c0]), b1 = __ldg(&qb[c0 + 1]);
            smU[SQ + r * 68 + c0]           = f2tf((acc[nt][0] + b0) * QK_SCALE);
            smU[SQ + r * 68 + c0 + 1]       = f2tf((acc[nt][1] + b1) * QK_SCALE);
            smU[SQ + (r + 8) * 68 + c0]     = f2tf((acc[nt][2] + b0) * QK_SCALE);
            smU[SQ + (r + 8) * 68 + c0 + 1] = f2tf((acc[nt][3] + b1) * QK_SCALE);
        }
    }
    __syncthreads();
    // pw -> SW (tf32)
#pragma unroll
    for (int it = 0; it < 2; it++) {
        int lin = it * 512 + tid;
        int r = lin >> 4, c4 = (lin & 15) * 4;
        *(uint4*)&smU[SW + r * 68 + c4] = f2tf4(*(const float4*)&pw[r * 64 + c4]);
    }

    for (int h = 0; h < 2; h++) {
        __syncthreads();
        // K/V head -> smem, pre-converted
#pragma unroll
        for (int it = 0; it < 4; it++) {
            int lin = it * 512 + tid;          // 2048 float4
            int m = lin >> 3, d4 = (lin & 7) * 4;
            int src = ((b * 2 + h) * 256 + m) * 32 + d4;
            *(uint4*)&smU[SK + m * 36 + d4] = f2tf4(*(const float4*)&g_kbuf[src]);
            *(uint4*)&smU[SV + m * 40 + d4] = f2tf4(*(const float4*)&g_vbuf[src]);
        }
        __syncthreads();

        // ---- logits: S[64,256] = q_h[64,32] @ K_h^T ----
        {
            int mt = w & 3, nh = w >> 2;       // nh: 4 groups of 64 cols
            float acc[8][4];
#pragma unroll
            for (int i = 0; i < 8; i++)
                acc[i][0] = acc[i][1] = acc[i][2] = acc[i][3] = 0.f;
#pragma unroll
            for (int ks = 0; ks < 4; ks++) {
                int kb = ks * 8;
                const unsigned* ab = &smU[SQ + (mt * 16 + lr) * 68 + h * 32 + kb + lc];
                unsigned af[4] = {ab[0], ab[8 * 68], ab[4], ab[8 * 68 + 4]};
#pragma unroll
                for (int nt = 0; nt < 8; nt++) {
                    int nb = nh * 64 + nt * 8;
                    const unsigned* bb = &smU[SK + (nb + lr) * 36 + kb + lc];
                    unsigned bf[2] = {bb[0], bb[4]};
                    mma8(acc[nt], af, bf);
                }
            }
#pragma unroll
            for (int nt = 0; nt < 8; nt++) {
                int nb = nh * 64 + nt * 8;
                int r = mt * 16 + lr, c0 = nb + 2 * lc;
                sm[SA + r * 260 + c0]           = acc[nt][0];
                sm[SA + r * 260 + c0 + 1]       = acc[nt][1];
                sm[SA + (r + 8) * 260 + c0]     = acc[nt][2];
                sm[SA + (r + 8) * 260 + c0 + 1] = acc[nt][3];
            }
        }
        __syncthreads();

        // ---- softmax + positional blend (warp w: rows w*4..w*4+3), writes tf32 ----
#pragma unroll
        for (int rr = 0; rr < 4; rr++) {
            int r = w * 4 + rr;
            const float* prow = &pos[(((size_t)(b * 2 + h)) * NN + n0 + r) * 256];
            float pv[8];
#pragma unroll
            for (int jj = 0; jj < 8; jj++) pv[jj] = __ldg(&prow[ln + jj * 32]);
            float* row = &sm[SA + r * 260];
            float vals[8];
            float mx = -1e30f;
#pragma unroll
            for (int jj = 0; jj < 8; jj++) {
                vals[jj] = row[ln + jj * 32];
                mx = fmaxf(mx, vals[jj]);
            }
#pragma unroll
            for (int off = 16; off; off >>= 1)
                mx = fmaxf(mx, __shfl_xor_sync(0xffffffffu, mx, off));
            float s = 0.f;
#pragma unroll
            for (int jj = 0; jj < 8; jj++) { vals[jj] = __expf(vals[jj] - mx); s += vals[jj]; }
#pragma unroll
            for (int off = 16; off; off >>= 1)
                s += __shfl_xor_sync(0xffffffffu, s, off);
            float inv = (1.f - a_) / s;
            unsigned* rowU = (unsigned*)row;
#pragma unroll
            for (int jj = 0; jj < 8; jj++)
                rowU[ln + jj * 32] = f2tf(vals[jj] * inv + a_ * pv[jj]);
        }
        __syncthreads();

        // ---- attn @ V: O[64,32] = attn[64,256] @ V[256,32] ----
        {
            int mt = w >> 2, ntp = w & 3;
            int nb = ntp * 8;
            float acc0[4] = {}, acc1[4] = {};
#pragma unroll 8
            for (int ks = 0; ks < 32; ks++) {
                int kb = ks * 8;
                const unsigned* ab = &smU[SA + (mt * 16 + lr) * 260 + kb + lc];
                unsigned af[4] = {ab[0], ab[8 * 260], ab[4], ab[8 * 260 + 4]};
                const unsigned* bb = &smU[SV + (kb + lc) * 40 + nb + lr];
                unsigned bf[2] = {bb[0], bb[4 * 40]};
                mma8((ks & 1) ? acc1 : acc0, af, bf);
            }
            int r = mt * 16 + lr, c0 = h * 32 + nb + 2 * lc;
            smU[SOB + r * 68 + c0]           = f2tf(acc0[0] + acc1[0]);
            smU[SOB + r * 68 + c0 + 1]       = f2tf(acc0[1] + acc1[1]);
            smU[SOB + (r + 8) * 68 + c0]     = f2tf(acc0[2] + acc1[2]);
            smU[SOB + (r + 8) * 68 + c0 + 1] = f2tf(acc0[3] + acc1[3]);
        }
    }
    __syncthreads();

    // ---- out-proj: D[64,64] = ob @ pw^T + pb ----
    {
        int mt = w >> 2, nq = w & 3;
        float acc[2][4] = {};
#pragma unroll
        for (int ks = 0; ks < 8; ks++) {
            int kb = ks * 8;
            const unsigned* ab = &smU[SOB + (mt * 16 + lr) * 68 + kb + lc];
            unsigned af[4] = {ab[0], ab[8 * 68], ab[4], ab[8 * 68 + 4]};
#pragma unroll
            for (int nt = 0; nt < 2; nt++) {
                int nb = nq * 16 + nt * 8;
                const unsigned* bb = &smU[SW + (nb + lr) * 68 + kb + lc];
                unsigned bf[2] = {bb[0], bb[4]};
                mma8(acc[nt], af, bf);
            }
        }
#pragma unroll
        for (int nt = 0; nt < 2; nt++) {
            int nb = nq * 16 + nt * 8;
            int r = mt * 16 + lr, c0 = nb + 2 * lc;
            float b0 = __ldg(&pb[c0]), b1 = __ldg(&pb[c0 + 1]);
            sm[SA + r * 68 + c0]           = acc[nt][0] + b0;
            sm[SA + r * 68 + c0 + 1]       = acc[nt][1] + b1;
            sm[SA + (r + 8) * 68 + c0]     = acc[nt][2] + b0;
            sm[SA + (r + 8) * 68 + c0 + 1] = acc[nt][3] + b1;
        }
    }
    __syncthreads();
#pragma unroll
    for (int it = 0; it < 2; it++) {
        int lin = it * 512 + tid;
        int r = lin >> 4, c4 = (lin & 15) * 4;
        *(float4*)&out[((size_t)b * NN + n0 + r) * 64 + c4] = *(float4*)&sm[SA + r * 68 + c4];
    }
}

// ---------------- launch ----------------
extern "C" void kernel_launch(void* const* d_in, const int* in_sizes, int n_in,
                              void* d_out, int out_size) {
    const float* x     = (const float*)d_in[0];
    const float* pos   = (const float*)d_in[1];
    const float* qw    = (const float*)d_in[2];
    const float* qb    = (const float*)d_in[3];
    const float* kvw   = (const float*)d_in[4];
    const float* kvb   = (const float*)d_in[5];
    const float* pw    = (const float*)d_in[6];
    const float* pb    = (const float*)d_in[7];
    const float* srw   = (const float*)d_in[8];
    const float* srb   = (const float*)d_in[9];
    const float* lng   = (const float*)d_in[10];
    const float* lnb   = (const float*)d_in[11];
    const float* alpha = (const float*)d_in[12];
    float* out = (float*)d_out;

    cudaFuncSetAttribute(k_attn, cudaFuncAttributeMaxDynamicSharedMemorySize,
                         SMF * 4);

    k_transpose<<<256, 256>>>(srw);
    k_conv<<<dim3(16, 16), 256>>>(x);
    k_lnkv<<<1024, 128>>>(srb, lng, lnb, kvw, kvb);
    k_attn<<<dim3(256, 4), 512, SMF * 4>>>(x, pos, qw, qb, pw, pb, alpha, out);
}

// round 7
// speedup vs baseline: 3.6380x; 1.0911x over previous
#include <cuda_runtime.h>
#include <math.h>

// Problem constants
#define BB   4
#define NN   16384
#define QK_SCALE 0.17677669529663687f   // 32^-0.5

// ---------------- scratch (device globals; no allocation) ----------------
__device__ float g_wt[4096 * 64];          // conv weights transposed [k][o]
__device__ float g_part[16 * 1024 * 64];   // conv split-K partials
__device__ float g_kbuf[8 * 256 * 32];     // K [b*2+h][m][d]
__device__ float g_vbuf[8 * 256 * 32];     // V [b*2+h][m][d]

// ---------------- mma helpers ----------------
__device__ __forceinline__ unsigned f2tf(float f) {
    unsigned u; asm("cvt.rna.tf32.f32 %0, %1;" : "=r"(u) : "f"(f)); return u;
}
__device__ __forceinline__ uint4 f2tf4(float4 v) {
    return make_uint4(f2tf(v.x), f2tf(v.y), f2tf(v.z), f2tf(v.w));
}
// pack: lo -> lower 16 bits, hi -> upper 16 bits
__device__ __forceinline__ unsigned packbf(float lo, float hi) {
    unsigned u; asm("cvt.rn.bf16x2.f32 %0, %1, %2;" : "=r"(u) : "f"(hi), "f"(lo)); return u;
}
__device__ __forceinline__ float bf_lo(unsigned u) { return __uint_as_float(u << 16); }
__device__ __forceinline__ float bf_hi(unsigned u) { return __uint_as_float(u & 0xffff0000u); }
__device__ __forceinline__ void mma8(float d[4], const unsigned a[4], const unsigned b[2]) {
    asm volatile(
        "mma.sync.aligned.m16n8k8.row.col.f32.tf32.tf32.f32 "
        "{%0,%1,%2,%3},{%4,%5,%6,%7},{%8,%9},{%0,%1,%2,%3};"
        : "+f"(d[0]), "+f"(d[1]), "+f"(d[2]), "+f"(d[3])
        : "r"(a[0]), "r"(a[1]), "r"(a[2]), "r"(a[3]), "r"(b[0]), "r"(b[1]));
}
__device__ __forceinline__ void mma16b(float d[4], const unsigned a[4], const unsigned b[2]) {
    asm volatile(
        "mma.sync.aligned.m16n8k16.row.col.f32.bf16.bf16.f32 "
        "{%0,%1,%2,%3},{%4,%5,%6,%7},{%8,%9},{%0,%1,%2,%3};"
        : "+f"(d[0]), "+f"(d[1]), "+f"(d[2]), "+f"(d[3])
        : "r"(a[0]), "r"(a[1]), "r"(a[2]), "r"(a[3]), "r"(b[0]), "r"(b[1]));
}

// ---------------- kernel 0: weight transpose ----------------
__global__ void __launch_bounds__(256) k_transpose(const float* __restrict__ srw) {
    int base = blockIdx.x * 256 + threadIdx.x;
#pragma unroll
    for (int it = 0; it < 4; it++) {
        int i = base + it * 65536;
        int o  = i & 63;
        int kg = i >> 6;
        int c   = kg & 63;
        int tap = kg >> 6;
        int kh = tap >> 3, kw = tap & 7;
        g_wt[i] = srw[((o * 64 + c) * 8 + kh) * 8 + kw];
    }
}

// ---------------- kernel 1: SR conv as split-K implicit GEMM ----------------
__global__ void __launch_bounds__(256) k_conv(const float* __restrict__ x) {
    __shared__ float As[16][68];
    __shared__ float Bs[16][68];
    int tid = threadIdx.x;
    int mtile = blockIdx.x, ks = blockIdx.y;
    int tm = tid >> 4, to = tid & 15;
    float acc[4][4] = {};

    int lm = tid >> 2, lkq = tid & 3;
    int gm = mtile * 64 + lm;
    int bb = gm >> 8, pos = gm & 255;
    int oh = pos >> 4, ow = pos & 15;
    int lkk = tid >> 4, lo4 = (tid & 15) * 4;

    for (int kc = 0; kc < 256; kc += 16) {
        int kg  = ks * 256 + kc + lkq * 4;
        int tap = kg >> 6, c = kg & 63;
        int kh = tap >> 3, kw = tap & 7;
        int pix = (oh * 8 + kh) * 128 + (ow * 8 + kw);
        float4 av = *(const float4*)&x[(bb * NN + pix) * 64 + c];
        As[lkq * 4 + 0][lm] = av.x;
        As[lkq * 4 + 1][lm] = av.y;
        As[lkq * 4 + 2][lm] = av.z;
        As[lkq * 4 + 3][lm] = av.w;
        float4 bv = *(const float4*)&g_wt[(ks * 256 + kc + lkk) * 64 + lo4];
        *(float4*)&Bs[lkk][lo4] = bv;
        __syncthreads();
#pragma unroll
        for (int kk = 0; kk < 16; kk++) {
            float4 a4 = *(float4*)&As[kk][tm * 4];
            float4 b4 = *(float4*)&Bs[kk][to * 4];
            acc[0][0] += a4.x * b4.x; acc[0][1] += a4.x * b4.y; acc[0][2] += a4.x * b4.z; acc[0][3] += a4.x * b4.w;
            acc[1][0] += a4.y * b4.x; acc[1][1] += a4.y * b4.y; acc[1][2] += a4.y * b4.z; acc[1][3] += a4.y * b4.w;
            acc[2][0] += a4.z * b4.x; acc[2][1] += a4.z * b4.y; acc[2][2] += a4.z * b4.z; acc[2][3] += a4.z * b4.w;
            acc[3][0] += a4.w * b4.x; acc[3][1] += a4.w * b4.y; acc[3][2] += a4.w * b4.z; acc[3][3] += a4.w * b4.w;
        }
        __syncthreads();
    }
    float* outp = &g_part[ks * 65536 + (mtile * 64) * 64];
#pragma unroll
    for (int i = 0; i < 4; i++)
        *(float4*)&outp[(tm * 4 + i) * 64 + to * 4] =
            make_float4(acc[i][0], acc[i][1], acc[i][2], acc[i][3]);
}

// ---------------- kernel 2: reduce partials + bias -> LN -> kv proj ----------------
__global__ void __launch_bounds__(128) k_lnkv(
    const float* __restrict__ srb, const float* __restrict__ lng,
    const float* __restrict__ lnb, const float* __restrict__ kvw,
    const float* __restrict__ kvb)
{
    __shared__ float snx[64];
    __shared__ float red[2][2];
    int m = blockIdx.x, tid = threadIdx.x;
    float v = 0.f;
    if (tid < 64) {
        v = srb[tid];
#pragma unroll
        for (int s = 0; s < 16; s++) v += g_part[s * 65536 + m * 64 + tid];
        float sv = v, sq = v * v;
#pragma unroll
        for (int off = 16; off; off >>= 1) {
            sv += __shfl_xor_sync(0xffffffffu, sv, off);
            sq += __shfl_xor_sync(0xffffffffu, sq, off);
        }
        if ((tid & 31) == 0) { red[tid >> 5][0] = sv; red[tid >> 5][1] = sq; }
    }
    __syncthreads();
    float mu  = (red[0][0] + red[1][0]) * (1.f / 64.f);
    float var = (red[0][1] + red[1][1]) * (1.f / 64.f) - mu * mu;
    float rstd = rsqrtf(var + 1e-5f);
    if (tid < 64) snx[tid] = (v - mu) * rstd * lng[tid] + lnb[tid];
    __syncthreads();

    int o = tid;
    float acc = kvb[o];
#pragma unroll
    for (int c4 = 0; c4 < 16; c4++) {
        float4 w = *(const float4*)&kvw[o * 64 + c4 * 4];
        acc += snx[c4 * 4 + 0] * w.x + snx[c4 * 4 + 1] * w.y
             + snx[c4 * 4 + 2] * w.z + snx[c4 * 4 + 3] * w.w;
    }
    int bb = m >> 8, mm = m & 255;
    int oo = o & 63, h = oo >> 5, d = oo & 31;
    float* dst = (o < 64) ? g_kbuf : g_vbuf;
    dst[((bb * 2 + h) * 256 + mm) * 32 + d] = acc;
}

// ---------------- kernel 3: fused attention, register-resident attn weights ----------------
// smem layout (4-byte words):
#define SQ    0        // q tf32 [r*68 + h*32+d], scale folded          (4352)
#define SOB   4352     // qw tf32 at start; attn-out tf32 [r*68+c]      (4352)
#define SK    8704     // K tf32 head [m*36+d]; pw tf32 [o*68+c] at end (9216)
#define SVH   17920    // V bf16-hi packed [k2*40 + n]                  (5120)
#define SVL   23040    // V bf16-lo packed [k2*40 + n]                  (5120)
#define SRED  28160    // x-tile tf32 at start; attn@V partials [nh][64][34] (8704)
#define SROW  36864    // row max/sum [64][8]                           (512)
#define SMFW  37376    // words -> 149504 bytes

__global__ void __launch_bounds__(512, 1) k_attn(
    const float* __restrict__ x,  const float* __restrict__ pos,
    const float* __restrict__ qw, const float* __restrict__ qb,
    const float* __restrict__ pw, const float* __restrict__ pb,
    const float* __restrict__ alpha, float* __restrict__ out)
{
    extern __shared__ float sm[];
    unsigned* smU = (unsigned*)sm;
    int tid = threadIdx.x, w = tid >> 5, ln = tid & 31;
    int lr = ln >> 2, lc = ln & 3;
    int b = blockIdx.y;
    int n0 = blockIdx.x * 64;
    float a_ = __ldg(alpha);

    // x tile -> SRED (tf32, stride 68), qw -> SOB (tf32)
#pragma unroll
    for (int it = 0; it < 2; it++) {
        int lin = it * 512 + tid;
        int r = lin >> 4, c4 = (lin & 15) * 4;
        *(uint4*)&smU[SRED + r * 68 + c4] =
            f2tf4(*(const float4*)&x[((size_t)b * NN + n0 + r) * 64 + c4]);
        *(uint4*)&smU[SOB + r * 68 + c4] =
            f2tf4(*(const float4*)&qw[r * 64 + c4]);
    }
    __syncthreads();

    // ---- q-proj: SQ = x @ qw^T (scale folded) ----
    {
        int mt = w >> 2, nq = w & 3;
        float acc[2][4] = {};
#pragma unroll
        for (int ks = 0; ks < 8; ks++) {
            const unsigned* ab = &smU[SRED + (mt * 16 + lr) * 68 + ks * 8 + lc];
            unsigned af[4] = {ab[0], ab[8 * 68], ab[4], ab[8 * 68 + 4]};
#pragma unroll
            for (int nt = 0; nt < 2; nt++) {
                const unsigned* bp = &smU[SOB + (nq * 16 + nt * 8 + lr) * 68 + ks * 8 + lc];
                unsigned bf[2] = {bp[0], bp[4]};
                mma8(acc[nt], af, bf);
            }
        }
#pragma unroll
        for (int nt = 0; nt < 2; nt++) {
            int c0 = nq * 16 + nt * 8 + 2 * lc;
            int r = mt * 16 + lr;
            float b0 = __ldg(&qb[c0]), b1 = __ldg(&qb[c0 + 1]);
            smU[SQ + r * 68 + c0]           = f2tf((acc[nt][0] + b0) * QK_SCALE);
            smU[SQ + r * 68 + c0 + 1]       = f2tf((acc[nt][1] + b1) * QK_SCALE);
            smU[SQ + (r + 8) * 68 + c0]     = f2tf((acc[nt][2] + b0) * QK_SCALE);
            smU[SQ + (r + 8) * 68 + c0 + 1] = f2tf((acc[nt][3] + b1) * QK_SCALE);
        }
    }
    __syncthreads();

    int mt = w & 3, nh = w >> 2;            // logits/attn decomposition
    int rowA = mt * 16 + lr;

    for (int h = 0; h < 2; h++) {
        int b2h = b * 2 + h;
        // stage K (tf32, stride 36) and V (bf16 split hi/lo, pairs along k, stride 40)
#pragma unroll
        for (int it = 0; it < 4; it++) {
            int lin = it * 512 + tid;
            int m = lin >> 3, d4 = (lin & 7) * 4;
            *(uint4*)&smU[SK + m * 36 + d4] =
                f2tf4(*(const float4*)&g_kbuf[(b2h * 256 + m) * 32 + d4]);
        }
#pragma unroll
        for (int it = 0; it < 8; it++) {
            int lin = it * 512 + tid;
            int k2 = lin >> 5, n = lin & 31;
            float v0 = g_vbuf[(b2h * 256 + 2 * k2) * 32 + n];
            float v1 = g_vbuf[(b2h * 256 + 2 * k2 + 1) * 32 + n];
            unsigned hi = packbf(v0, v1);
            smU[SVH + k2 * 40 + n] = hi;
            smU[SVL + k2 * 40 + n] = packbf(v0 - bf_lo(hi), v1 - bf_hi(hi));
        }
        __syncthreads();

        // ---- logits for rows [mt*16..+15], cols [nh*64..+63] (in registers) ----
        float acc[8][4];
#pragma unroll
        for (int i = 0; i < 8; i++)
            acc[i][0] = acc[i][1] = acc[i][2] = acc[i][3] = 0.f;
#pragma unroll
        for (int ks = 0; ks < 4; ks++) {
            const unsigned* ab = &smU[SQ + rowA * 68 + h * 32 + ks * 8 + lc];
            unsigned af[4] = {ab[0], ab[8 * 68], ab[4], ab[8 * 68 + 4]};
#pragma unroll
            for (int nt = 0; nt < 8; nt++) {
                const unsigned* bp = &smU[SK + (nh * 64 + nt * 8 + lr) * 36 + ks * 8 + lc];
                unsigned bf[2] = {bp[0], bp[4]};
                mma8(acc[nt], af, bf);
            }
        }

        // ---- softmax (register + tiny smem cross-warp exchange) ----
        float mx0 = -1e30f, mx1 = -1e30f;
#pragma unroll
        for (int nt = 0; nt < 8; nt++) {
            mx0 = fmaxf(mx0, fmaxf(acc[nt][0], acc[nt][1]));
            mx1 = fmaxf(mx1, fmaxf(acc[nt][2], acc[nt][3]));
        }
        mx0 = fmaxf(mx0, __shfl_xor_sync(0xffffffffu, mx0, 1));
        mx0 = fmaxf(mx0, __shfl_xor_sync(0xffffffffu, mx0, 2));
        mx1 = fmaxf(mx1, __shfl_xor_sync(0xffffffffu, mx1, 1));
        mx1 = fmaxf(mx1, __shfl_xor_sync(0xffffffffu, mx1, 2));
        if (lc == 0) {
            sm[SROW + rowA * 8 + nh]       = mx0;
            sm[SROW + (rowA + 8) * 8 + nh] = mx1;
        }
        __syncthreads();
        float4 m40 = *(float4*)&sm[SROW + rowA * 8];
        float4 m41 = *(float4*)&sm[SROW + (rowA + 8) * 8];
        float gm0 = fmaxf(fmaxf(m40.x, m40.y), fmaxf(m40.z, m40.w));
        float gm1 = fmaxf(fmaxf(m41.x, m41.y), fmaxf(m41.z, m41.w));
        float s0 = 0.f, s1 = 0.f;
#pragma unroll
        for (int nt = 0; nt < 8; nt++) {
            acc[nt][0] = __expf(acc[nt][0] - gm0); s0 += acc[nt][0];
            acc[nt][1] = __expf(acc[nt][1] - gm0); s0 += acc[nt][1];
            acc[nt][2] = __expf(acc[nt][2] - gm1); s1 += acc[nt][2];
            acc[nt][3] = __expf(acc[nt][3] - gm1); s1 += acc[nt][3];
        }
        s0 += __shfl_xor_sync(0xffffffffu, s0, 1);
        s0 += __shfl_xor_sync(0xffffffffu, s0, 2);
        s1 += __shfl_xor_sync(0xffffffffu, s1, 1);
        s1 += __shfl_xor_sync(0xffffffffu, s1, 2);
        if (lc == 0) {
            sm[SROW + rowA * 8 + 4 + nh]       = s0;
            sm[SROW + (rowA + 8) * 8 + 4 + nh] = s1;
        }
        __syncthreads();
        float4 s40 = *(float4*)&sm[SROW + rowA * 8 + 4];
        float4 s41 = *(float4*)&sm[SROW + (rowA + 8) * 8 + 4];
        float inv0 = (1.f - a_) / (s40.x + s40.y + s40.z + s40.w);
        float inv1 = (1.f - a_) / (s41.x + s41.y + s41.z + s41.w);

        // ---- blend + split-bf16 pack + attn@V partial (k-range nh*64..+63) ----
        const float* pr0 = &pos[((size_t)b2h * NN + n0 + rowA) * 256];
        const float* pr1 = pr0 + 8 * 256;
        float accO[4][4];
#pragma unroll
        for (int i = 0; i < 4; i++)
            accO[i][0] = accO[i][1] = accO[i][2] = accO[i][3] = 0.f;
#pragma unroll
        for (int kk = 0; kk < 4; kk++) {
            unsigned afh[4], afl[4];
#pragma unroll
            for (int q = 0; q < 2; q++) {
                int nt = 2 * kk + q;
                int cb = nh * 64 + nt * 8 + 2 * lc;
                float2 p0 = __ldg((const float2*)&pr0[cb]);
                float2 p1 = __ldg((const float2*)&pr1[cb]);
                float w00 = acc[nt][0] * inv0 + a_ * p0.x;
                float w01 = acc[nt][1] * inv0 + a_ * p0.y;
                float w10 = acc[nt][2] * inv1 + a_ * p1.x;
                float w11 = acc[nt][3] * inv1 + a_ * p1.y;
                unsigned h0 = packbf(w00, w01);
                unsigned h1 = packbf(w10, w11);
                afh[2 * q]     = h0;
                afh[2 * q + 1] = h1;
                afl[2 * q]     = packbf(w00 - bf_lo(h0), w01 - bf_hi(h0));
                afl[2 * q + 1] = packbf(w10 - bf_lo(h1), w11 - bf_hi(h1));
            }
            int k2b = nh * 32 + kk * 8;
#pragma unroll
            for (int ntv = 0; ntv < 4; ntv++) {
                const unsigned* bph = &smU[SVH + (k2b + lc) * 40 + ntv * 8 + lr];
                const unsigned* bpl = &smU[SVL + (k2b + lc) * 40 + ntv * 8 + lr];
                unsigned bh[2] = {bph[0], bph[4 * 40]};
                unsigned bl[2] = {bpl[0], bpl[4 * 40]};
                mma16b(accO[ntv], afh, bh);
                mma16b(accO[ntv], afh, bl);
                mma16b(accO[ntv], afl, bh);
            }
        }
        // write partials [nh][row][col]
#pragma unroll
        for (int ntv = 0; ntv < 4; ntv++) {
            int cc = ntv * 8 + 2 * lc;
            *(float2*)&sm[SRED + nh * 2176 + rowA * 34 + cc] =
                make_float2(accO[ntv][0], accO[ntv][1]);
            *(float2*)&sm[SRED + nh * 2176 + (rowA + 8) * 34 + cc] =
                make_float2(accO[ntv][2], accO[ntv][3]);
        }
        __syncthreads();
        // reduce 4 partials -> SOB (tf32)
#pragma unroll
        for (int i = 0; i < 2; i++) {
            int p = i * 512 + tid;
            int r = p >> 4, c2 = (p & 15) * 2;
            float sx = 0.f, sy = 0.f;
#pragma unroll
            for (int g = 0; g < 4; g++) {
                float2 t = *(float2*)&sm[SRED + g * 2176 + r * 34 + c2];
                sx += t.x; sy += t.y;
            }
            smU[SOB + r * 68 + h * 32 + c2]     = f2tf(sx);
            smU[SOB + r * 68 + h * 32 + c2 + 1] = f2tf(sy);
        }
        __syncthreads();
    }

    // pw -> SK region (tf32, stride 68)
#pragma unroll
    for (int it = 0; it < 2; it++) {
        int lin = it * 512 + tid;
        int r = lin >> 4, c4 = (lin & 15) * 4;
        *(uint4*)&smU[SK + r * 68 + c4] = f2tf4(*(const float4*)&pw[r * 64 + c4]);
    }
    __syncthreads();

    // ---- out-proj: out = attn_out @ pw^T + pb (direct STG) ----
    {
        int mtp = w >> 2, nq = w & 3;
        float acc[2][4] = {};
#pragma unroll
        for (int ks = 0; ks < 8; ks++) {
            const unsigned* ab = &smU[SOB + (mtp * 16 + lr) * 68 + ks * 8 + lc];
            unsigned af[4] = {ab[0], ab[8 * 68], ab[4], ab[8 * 68 + 4]};
#pragma unroll
            for (int nt = 0; nt < 2; nt++) {
                const unsigned* bp = &smU[SK + (nq * 16 + nt * 8 + lr) * 68 + ks * 8 + lc];
                unsigned bf[2] = {bp[0], bp[4]};
                mma8(acc[nt], af, bf);
            }
        }
#pragma unroll
        for (int nt = 0; nt < 2; nt++) {
            int c0 = nq * 16 + nt * 8 + 2 * lc;
            int r = mtp * 16 + lr;
            float b0 = __ldg(&pb[c0]), b1 = __ldg(&pb[c0 + 1]);
            *(float2*)&out[((size_t)b * NN + n0 + r) * 64 + c0] =
                make_float2(acc[nt][0] + b0, acc[nt][1] + b1);
            *(float2*)&out[((size_t)b * NN + n0 + r + 8) * 64 + c0] =
                make_float2(acc[nt][2] + b0, acc[nt][3] + b1);
        }
    }
}

// ---------------- launch ----------------
extern "C" void kernel_launch(void* const* d_in, const int* in_sizes, int n_in,
                              void* d_out, int out_size) {
    const float* x     = (const float*)d_in[0];
    const float* pos   = (const float*)d_in[1];
    const float* qw    = (const float*)d_in[2];
    const float* qb    = (const float*)d_in[3];
    const float* kvw   = (const float*)d_in[4];
    const float* kvb   = (const float*)d_in[5];
    const float* pw    = (const float*)d_in[6];
    const float* pb    = (const float*)d_in[7];
    const float* srw   = (const float*)d_in[8];
    const float* srb   = (const float*)d_in[9];
    const float* lng   = (const float*)d_in[10];
    const float* lnb   = (const float*)d_in[11];
    const float* alpha = (const float*)d_in[12];
    float* out = (float*)d_out;

    cudaFuncSetAttribute(k_attn, cudaFuncAttributeMaxDynamicSharedMemorySize,
                         SMFW * 4);

    k_transpose<<<256, 256>>>(srw);
    k_conv<<<dim3(16, 16), 256>>>(x);
    k_lnkv<<<1024, 128>>>(srb, lng, lnb, kvw, kvb);
    k_attn<<<dim3(256, 4), 512, SMFW * 4>>>(x, pos, qw, qb, pw, pb, alpha, out);
}

// round 8
// speedup vs baseline: 3.7358x; 1.0269x over previous
#include <cuda_runtime.h>
#include <math.h>

// Problem constants
#define BB   4
#define NN   16384
#define QK_SCALE 0.17677669529663687f   // 32^-0.5

// ---------------- scratch (device globals; no allocation) ----------------
__device__ float g_wt[64 * 4096];          // conv weights transposed [o][k]
__device__ float g_part[16 * 1024 * 64];   // conv split-K partials
__device__ float g_kbuf[8 * 256 * 32];     // K [b*2+h][m][d]
__device__ float g_vbuf[8 * 256 * 32];     // V [b*2+h][m][d]

// ---------------- mma helpers ----------------
__device__ __forceinline__ unsigned f2tf(float f) {
    unsigned u; asm("cvt.rna.tf32.f32 %0, %1;" : "=r"(u) : "f"(f)); return u;
}
__device__ __forceinline__ uint4 f2tf4(float4 v) {
    return make_uint4(f2tf(v.x), f2tf(v.y), f2tf(v.z), f2tf(v.w));
}
// pack: lo -> lower 16 bits, hi -> upper 16 bits
__device__ __forceinline__ unsigned packbf(float lo, float hi) {
    unsigned u; asm("cvt.rn.bf16x2.f32 %0, %1, %2;" : "=r"(u) : "f"(hi), "f"(lo)); return u;
}
__device__ __forceinline__ float bf_lo(unsigned u) { return __uint_as_float(u << 16); }
__device__ __forceinline__ float bf_hi(unsigned u) { return __uint_as_float(u & 0xffff0000u); }
__device__ __forceinline__ void mma8(float d[4], const unsigned a[4], const unsigned b[2]) {
    asm volatile(
        "mma.sync.aligned.m16n8k8.row.col.f32.tf32.tf32.f32 "
        "{%0,%1,%2,%3},{%4,%5,%6,%7},{%8,%9},{%0,%1,%2,%3};"
        : "+f"(d[0]), "+f"(d[1]), "+f"(d[2]), "+f"(d[3])
        : "r"(a[0]), "r"(a[1]), "r"(a[2]), "r"(a[3]), "r"(b[0]), "r"(b[1]));
}
__device__ __forceinline__ void mma16b(float d[4], const unsigned a[4], const unsigned b[2]) {
    asm volatile(
        "mma.sync.aligned.m16n8k16.row.col.f32.bf16.bf16.f32 "
        "{%0,%1,%2,%3},{%4,%5,%6,%7},{%8,%9},{%0,%1,%2,%3};"
        : "+f"(d[0]), "+f"(d[1]), "+f"(d[2]), "+f"(d[3])
        : "r"(a[0]), "r"(a[1]), "r"(a[2]), "r"(a[3]), "r"(b[0]), "r"(b[1]));
}

// ---------------- kernel 0: weight transpose  srw[o][c][kh][kw] -> g_wt[o][kg=tap*64+c]
__global__ void __launch_bounds__(256) k_transpose(const float* __restrict__ srw) {
    int base = blockIdx.x * 256 + threadIdx.x;
#pragma unroll
    for (int it = 0; it < 4; it++) {
        int i = base + it * 65536;
        int o   = i >> 12;
        int kg  = i & 4095;
        int tap = kg >> 6, c = kg & 63;
        int kh = tap >> 3, kw = tap & 7;
        g_wt[i] = srw[((o * 64 + c) * 8 + kh) * 8 + kw];
    }
}

// ---------------- kernel 1: SR conv as split-K implicit GEMM (tf32 mma) ----------------
__global__ void __launch_bounds__(256) k_conv(const float* __restrict__ x) {
    __shared__ unsigned As[64 * 20];
    __shared__ unsigned Bsm[64 * 20];
    int tid = threadIdx.x, w = tid >> 5, ln = tid & 31;
    int lr = ln >> 2, lc = ln & 3;
    int mtile = blockIdx.x, ks = blockIdx.y;
    int mt = w & 3, nq = w >> 2;
    float acc[4][4] = {};

    int lm = tid >> 2, lkq = tid & 3;        // A/B load coords
    int gm = mtile * 64 + lm;
    int bb = gm >> 8, pos = gm & 255;
    int oh = pos >> 4, ow = pos & 15;

    for (int kc = 0; kc < 256; kc += 16) {
        int kg  = ks * 256 + kc + lkq * 4;
        int tap = kg >> 6, c = kg & 63;
        int kh = tap >> 3, kw = tap & 7;
        int pix = (oh * 8 + kh) * 128 + (ow * 8 + kw);
        *(uint4*)&As[lm * 20 + lkq * 4] =
            f2tf4(*(const float4*)&x[(bb * NN + pix) * 64 + c]);
        *(uint4*)&Bsm[lm * 20 + lkq * 4] =
            f2tf4(*(const float4*)&g_wt[lm * 4096 + ks * 256 + kc + lkq * 4]);
        __syncthreads();
#pragma unroll
        for (int kb = 0; kb < 16; kb += 8) {
            const unsigned* ab = &As[(mt * 16 + lr) * 20 + kb + lc];
            unsigned af[4] = {ab[0], ab[8 * 20], ab[4], ab[8 * 20 + 4]};
#pragma unroll
            for (int nt = 0; nt < 4; nt++) {
                const unsigned* bp = &Bsm[(nq * 32 + nt * 8 + lr) * 20 + kb + lc];
                unsigned bf[2] = {bp[0], bp[4]};
                mma8(acc[nt], af, bf);
            }
        }
        __syncthreads();
    }
    float* outp = &g_part[ks * 65536 + (mtile * 64) * 64];
#pragma unroll
    for (int nt = 0; nt < 4; nt++) {
        int r = mt * 16 + lr, c0 = nq * 32 + nt * 8 + 2 * lc;
        *(float2*)&outp[r * 64 + c0]       = make_float2(acc[nt][0], acc[nt][1]);
        *(float2*)&outp[(r + 8) * 64 + c0] = make_float2(acc[nt][2], acc[nt][3]);
    }
}

// ---------------- kernel 2: reduce partials + bias -> LN -> kv proj ----------------
__global__ void __launch_bounds__(128) k_lnkv(
    const float* __restrict__ srb, const float* __restrict__ lng,
    const float* __restrict__ lnb, const float* __restrict__ kvw,
    const float* __restrict__ kvb)
{
    __shared__ float snx[64];
    __shared__ float red[2][2];
    int m = blockIdx.x, tid = threadIdx.x;
    float v = 0.f;
    if (tid < 64) {
        v = srb[tid];
#pragma unroll
        for (int s = 0; s < 16; s++) v += g_part[s * 65536 + m * 64 + tid];
        float sv = v, sq = v * v;
#pragma unroll
        for (int off = 16; off; off >>= 1) {
            sv += __shfl_xor_sync(0xffffffffu, sv, off);
            sq += __shfl_xor_sync(0xffffffffu, sq, off);
        }
        if ((tid & 31) == 0) { red[tid >> 5][0] = sv; red[tid >> 5][1] = sq; }
    }
    __syncthreads();
    float mu  = (red[0][0] + red[1][0]) * (1.f / 64.f);
    float var = (red[0][1] + red[1][1]) * (1.f / 64.f) - mu * mu;
    float rstd = rsqrtf(var + 1e-5f);
    if (tid < 64) snx[tid] = (v - mu) * rstd * lng[tid] + lnb[tid];
    __syncthreads();

    int o = tid;
    float acc = kvb[o];
#pragma unroll
    for (int c4 = 0; c4 < 16; c4++) {
        float4 w = *(const float4*)&kvw[o * 64 + c4 * 4];
        acc += snx[c4 * 4 + 0] * w.x + snx[c4 * 4 + 1] * w.y
             + snx[c4 * 4 + 2] * w.z + snx[c4 * 4 + 3] * w.w;
    }
    int bb = m >> 8, mm = m & 255;
    int oo = o & 63, h = oo >> 5, d = oo & 31;
    float* dst = (o < 64) ? g_kbuf : g_vbuf;
    dst[((bb * 2 + h) * 256 + mm) * 32 + d] = acc;
}

// ---------------- kernel 3: fused attention, 32-row tiles, 2 CTAs/SM ----------------
// smem layout (4-byte words):
#define SQ    0       // q tf32 [r*68 + h*32+d] (32 rows)               (2176)
#define SOB   2176    // attn-out tf32 [r*68+c] (32 rows)               (2176)
#define SK    4352    // qw@start [o*68+c]; K [m*36+d]; partials [4][32][34]; pw@end (9216)
#define SVH   13568   // x-tile@start [r*68+c]; V bf16-hi [k2*40+n]     (5120)
#define SVL   18688   // V bf16-lo [k2*40+n]                            (5120)
#define SROW  23808   // row max/sum [32][8]                            (256)
#define SMFW  24064   // words -> 96256 bytes

__global__ void __launch_bounds__(256, 2) k_attn(
    const float* __restrict__ x,  const float* __restrict__ pos,
    const float* __restrict__ qw, const float* __restrict__ qb,
    const float* __restrict__ pw, const float* __restrict__ pb,
    const float* __restrict__ alpha, float* __restrict__ out)
{
    extern __shared__ float sm[];
    unsigned* smU = (unsigned*)sm;
    int tid = threadIdx.x, w = tid >> 5, ln = tid & 31;
    int lr = ln >> 2, lc = ln & 3;
    int b = blockIdx.y;
    int n0 = blockIdx.x * 32;
    float a_ = __ldg(alpha);

    // x tile (32 rows) -> SVH region (tf32, stride 68); qw -> SK region
#pragma unroll
    for (int it = 0; it < 2; it++) {
        int lin = it * 256 + tid;              // 0..511
        int r = lin >> 4, c4 = (lin & 15) * 4;
        *(uint4*)&smU[SVH + r * 68 + c4] =
            f2tf4(*(const float4*)&x[((size_t)b * NN + n0 + r) * 64 + c4]);
    }
#pragma unroll
    for (int it = 0; it < 4; it++) {
        int lin = it * 256 + tid;              // 0..1023
        int r = lin >> 4, c4 = (lin & 15) * 4;
        *(uint4*)&smU[SK + r * 68 + c4] =
            f2tf4(*(const float4*)&qw[r * 64 + c4]);
    }
    __syncthreads();

    // ---- q-proj: SQ[32,64] = x @ qw^T (scale folded) ----
    {
        int mtp = w & 1, nq = w >> 1;
        float acc[2][4] = {};
#pragma unroll
        for (int ks = 0; ks < 8; ks++) {
            const unsigned* ab = &smU[SVH + (mtp * 16 + lr) * 68 + ks * 8 + lc];
            unsigned af[4] = {ab[0], ab[8 * 68], ab[4], ab[8 * 68 + 4]};
#pragma unroll
            for (int nt = 0; nt < 2; nt++) {
                const unsigned* bp = &smU[SK + (nq * 16 + nt * 8 + lr) * 68 + ks * 8 + lc];
                unsigned bf[2] = {bp[0], bp[4]};
                mma8(acc[nt], af, bf);
            }
        }
#pragma unroll
        for (int nt = 0; nt < 2; nt++) {
            int c0 = nq * 16 + nt * 8 + 2 * lc;
            int r = mtp * 16 + lr;
            float b0 = __ldg(&qb[c0]), b1 = __ldg(&qb[c0 + 1]);
            smU[SQ + r * 68 + c0]           = f2tf((acc[nt][0] + b0) * QK_SCALE);
            smU[SQ + r * 68 + c0 + 1]       = f2tf((acc[nt][1] + b1) * QK_SCALE);
            smU[SQ + (r + 8) * 68 + c0]     = f2tf((acc[nt][2] + b0) * QK_SCALE);
            smU[SQ + (r + 8) * 68 + c0 + 1] = f2tf((acc[nt][3] + b1) * QK_SCALE);
        }
    }
    __syncthreads();

    int mt = w & 1, nh = w >> 1;               // logits/attn decomposition
    int rowA = mt * 16 + lr;                   // 0..31

    for (int h = 0; h < 2; h++) {
        int b2h = b * 2 + h;
        // stage K (tf32, stride 36, overwrites qw/partials) and V (bf16 hi/lo, stride 40)
#pragma unroll
        for (int it = 0; it < 8; it++) {
            int lin = it * 256 + tid;          // 0..2047 float4
            int m = lin >> 3, d4 = (lin & 7) * 4;
            *(uint4*)&smU[SK + m * 36 + d4] =
                f2tf4(*(const float4*)&g_kbuf[(b2h * 256 + m) * 32 + d4]);
        }
#pragma unroll
        for (int it = 0; it < 16; it++) {
            int lin = it * 256 + tid;          // 0..4095
            int k2 = lin >> 5, n = lin & 31;
            float v0 = g_vbuf[(b2h * 256 + 2 * k2) * 32 + n];
            float v1 = g_vbuf[(b2h * 256 + 2 * k2 + 1) * 32 + n];
            unsigned hi = packbf(v0, v1);
            smU[SVH + k2 * 40 + n] = hi;
            smU[SVL + k2 * 40 + n] = packbf(v0 - bf_lo(hi), v1 - bf_hi(hi));
        }
        __syncthreads();

        // ---- logits rows [mt*16..+15], cols [nh*64..+63] (registers) ----
        float acc[8][4];
#pragma unroll
        for (int i = 0; i < 8; i++)
            acc[i][0] = acc[i][1] = acc[i][2] = acc[i][3] = 0.f;
#pragma unroll
        for (int ks = 0; ks < 4; ks++) {
            const unsigned* ab = &smU[SQ + rowA * 68 + h * 32 + ks * 8 + lc];
            unsigned af[4] = {ab[0], ab[8 * 68], ab[4], ab[8 * 68 + 4]};
#pragma unroll
            for (int nt = 0; nt < 8; nt++) {
                const unsigned* bp = &smU[SK + (nh * 64 + nt * 8 + lr) * 36 + ks * 8 + lc];
                unsigned bf[2] = {bp[0], bp[4]};
                mma8(acc[nt], af, bf);
            }
        }

        // ---- softmax (register + cross-warp exchange) ----
        float mx0 = -1e30f, mx1 = -1e30f;
#pragma unroll
        for (int nt = 0; nt < 8; nt++) {
            mx0 = fmaxf(mx0, fmaxf(acc[nt][0], acc[nt][1]));
            mx1 = fmaxf(mx1, fmaxf(acc[nt][2], acc[nt][3]));
        }
        mx0 = fmaxf(mx0, __shfl_xor_sync(0xffffffffu, mx0, 1));
        mx0 = fmaxf(mx0, __shfl_xor_sync(0xffffffffu, mx0, 2));
        mx1 = fmaxf(mx1, __shfl_xor_sync(0xffffffffu, mx1, 1));
        mx1 = fmaxf(mx1, __shfl_xor_sync(0xffffffffu, mx1, 2));
        if (lc == 0) {
            sm[SROW + rowA * 8 + nh]       = mx0;
            sm[SROW + (rowA + 8) * 8 + nh] = mx1;
        }
        __syncthreads();
        float4 m40 = *(float4*)&sm[SROW + rowA * 8];
        float4 m41 = *(float4*)&sm[SROW + (rowA + 8) * 8];
        float gm0 = fmaxf(fmaxf(m40.x, m40.y), fmaxf(m40.z, m40.w));
        float gm1 = fmaxf(fmaxf(m41.x, m41.y), fmaxf(m41.z, m41.w));
        float s0 = 0.f, s1 = 0.f;
#pragma unroll
        for (int nt = 0; nt < 8; nt++) {
            acc[nt][0] = __expf(acc[nt][0] - gm0); s0 += acc[nt][0];
            acc[nt][1] = __expf(acc[nt][1] - gm0); s0 += acc[nt][1];
            acc[nt][2] = __expf(acc[nt][2] - gm1); s1 += acc[nt][2];
            acc[nt][3] = __expf(acc[nt][3] - gm1); s1 += acc[nt][3];
        }
        s0 += __shfl_xor_sync(0xffffffffu, s0, 1);
        s0 += __shfl_xor_sync(0xffffffffu, s0, 2);
        s1 += __shfl_xor_sync(0xffffffffu, s1, 1);
        s1 += __shfl_xor_sync(0xffffffffu, s1, 2);
        if (lc == 0) {
            sm[SROW + rowA * 8 + 4 + nh]       = s0;
            sm[SROW + (rowA + 8) * 8 + 4 + nh] = s1;
        }
        __syncthreads();
        float4 s40 = *(float4*)&sm[SROW + rowA * 8 + 4];
        float4 s41 = *(float4*)&sm[SROW + (rowA + 8) * 8 + 4];
        float inv0 = (1.f - a_) / (s40.x + s40.y + s40.z + s40.w);
        float inv1 = (1.f - a_) / (s41.x + s41.y + s41.z + s41.w);

        // ---- blend + split-bf16 pack + attn@V partial (k-range nh*64..+63) ----
        const float* pr0 = &pos[((size_t)b2h * NN + n0 + rowA) * 256];
        const float* pr1 = pr0 + 8 * 256;
        float accO[4][4];
#pragma unroll
        for (int i = 0; i < 4; i++)
            accO[i][0] = accO[i][1] = accO[i][2] = accO[i][3] = 0.f;
#pragma unroll
        for (int kk = 0; kk < 4; kk++) {
            unsigned afh[4], afl[4];
#pragma unroll
            for (int q = 0; q < 2; q++) {
                int nt = 2 * kk + q;
                int cb = nh * 64 + nt * 8 + 2 * lc;
                float2 p0 = __ldg((const float2*)&pr0[cb]);
                float2 p1 = __ldg((const float2*)&pr1[cb]);
                float w00 = acc[nt][0] * inv0 + a_ * p0.x;
                float w01 = acc[nt][1] * inv0 + a_ * p0.y;
                float w10 = acc[nt][2] * inv1 + a_ * p1.x;
                float w11 = acc[nt][3] * inv1 + a_ * p1.y;
                unsigned h0 = packbf(w00, w01);
                unsigned h1 = packbf(w10, w11);
                afh[2 * q]     = h0;
                afh[2 * q + 1] = h1;
                afl[2 * q]     = packbf(w00 - bf_lo(h0), w01 - bf_hi(h0));
                afl[2 * q + 1] = packbf(w10 - bf_lo(h1), w11 - bf_hi(h1));
            }
            int k2b = nh * 32 + kk * 8;
#pragma unroll
            for (int ntv = 0; ntv < 4; ntv++) {
                const unsigned* bph = &smU[SVH + (k2b + lc) * 40 + ntv * 8 + lr];
                const unsigned* bpl = &smU[SVL + (k2b + lc) * 40 + ntv * 8 + lr];
                unsigned bh[2] = {bph[0], bph[4 * 40]};
                unsigned bl[2] = {bpl[0], bpl[4 * 40]};
                mma16b(accO[ntv], afh, bh);
                mma16b(accO[ntv], afh, bl);
                mma16b(accO[ntv], afl, bh);
            }
        }
        // write partials into SK region [nh][32][34] (K reads done; SROW syncs above)
#pragma unroll
        for (int ntv = 0; ntv < 4; ntv++) {
            int cc = ntv * 8 + 2 * lc;
            *(float2*)&sm[SK + nh * 1088 + rowA * 34 + cc] =
                make_float2(accO[ntv][0], accO[ntv][1]);
            *(float2*)&sm[SK + nh * 1088 + (rowA + 8) * 34 + cc] =
                make_float2(accO[ntv][2], accO[ntv][3]);
        }
        __syncthreads();
        // reduce 4 partials -> SOB (tf32)
#pragma unroll
        for (int i = 0; i < 2; i++) {
            int p = i * 256 + tid;
            int r = p >> 4, c2 = (p & 15) * 2;
            float sx = 0.f, sy = 0.f;
#pragma unroll
            for (int g = 0; g < 4; g++) {
                float2 t = *(float2*)&sm[SK + g * 1088 + r * 34 + c2];
                sx += t.x; sy += t.y;
            }
            smU[SOB + r * 68 + h * 32 + c2]     = f2tf(sx);
            smU[SOB + r * 68 + h * 32 + c2 + 1] = f2tf(sy);
        }
        __syncthreads();
    }

    // pw -> SK region (tf32, stride 68)
#pragma unroll
    for (int it = 0; it < 4; it++) {
        int lin = it * 256 + tid;
        int r = lin >> 4, c4 = (lin & 15) * 4;
        *(uint4*)&smU[SK + r * 68 + c4] = f2tf4(*(const float4*)&pw[r * 64 + c4]);
    }
    __syncthreads();

    // ---- out-proj: out = attn_out @ pw^T + pb (direct STG) ----
    {
        int mtp = w & 1, nq = w >> 1;
        float acc[2][4] = {};
#pragma unroll
        for (int ks = 0; ks < 8; ks++) {
            const unsigned* ab = &smU[SOB + (mtp * 16 + lr) * 68 + ks * 8 + lc];
            unsigned af[4] = {ab[0], ab[8 * 68], ab[4], ab[8 * 68 + 4]};
#pragma unroll
            for (int nt = 0; nt < 2; nt++) {
                const unsigned* bp = &smU[SK + (nq * 16 + nt * 8 + lr) * 68 + ks * 8 + lc];
                unsigned bf[2] = {bp[0], bp[4]};
                mma8(acc[nt], af, bf);
            }
        }
#pragma unroll
        for (int nt = 0; nt < 2; nt++) {
            int c0 = nq * 16 + nt * 8 + 2 * lc;
            int r = mtp * 16 + lr;
            float b0 = __ldg(&pb[c0]), b1 = __ldg(&pb[c0 + 1]);
            *(float2*)&out[((size_t)b * NN + n0 + r) * 64 + c0] =
                make_float2(acc[nt][0] + b0, acc[nt][1] + b1);
            *(float2*)&out[((size_t)b * NN + n0 + r + 8) * 64 + c0] =
                make_float2(acc[nt][2] + b0, acc[nt][3] + b1);
        }
    }
}

// ---------------- launch ----------------
extern "C" void kernel_launch(void* const* d_in, const int* in_sizes, int n_in,
                              void* d_out, int out_size) {
    const float* x     = (const float*)d_in[0];
    const float* pos   = (const float*)d_in[1];
    const float* qw    = (const float*)d_in[2];
    const float* qb    = (const float*)d_in[3];
    const float* kvw   = (const float*)d_in[4];
    const float* kvb   = (const float*)d_in[5];
    const float* pw    = (const float*)d_in[6];
    const float* pb    = (const float*)d_in[7];
    const float* srw   = (const float*)d_in[8];
    const float* srb   = (const float*)d_in[9];
    const float* lng   = (const float*)d_in[10];
    const float* lnb   = (const float*)d_in[11];
    const float* alpha = (const float*)d_in[12];
    float* out = (float*)d_out;

    cudaFuncSetAttribute(k_attn, cudaFuncAttributeMaxDynamicSharedMemorySize,
                         SMFW * 4);

    k_transpose<<<256, 256>>>(srw);
    k_conv<<<dim3(16, 16), 256>>>(x);
    k_lnkv<<<1024, 128>>>(srb, lng, lnb, kvw, kvb);
    k_attn<<<dim3(512, 4), 256, SMFW * 4>>>(x, pos, qw, qb, pw, pb, alpha, out);
}

// round 9
// speedup vs baseline: 3.8932x; 1.0421x over previous
#include <cuda_runtime.h>
#include <math.h>

// Problem constants
#define BB   4
#define NN   16384
#define QK_SCALE 0.17677669529663687f   // 32^-0.5

// ---------------- scratch (device globals; no allocation) ----------------
__device__ float    g_wt[64 * 4096];         // conv weights transposed [o][k]
__device__ float    g_part[16 * 1024 * 64];  // conv split-K partials
__device__ unsigned g_ktf[8 * 256 * 32];     // K tf32 [b*2+h][m][d]
__device__ unsigned g_vhi[8 * 128 * 32];     // V bf16-hi pairs [b*2+h][k2][n]
__device__ unsigned g_vlo[8 * 128 * 32];     // V bf16-lo pairs [b*2+h][k2][n]

// ---------------- mma helpers ----------------
__device__ __forceinline__ unsigned f2tf(float f) {
    unsigned u; asm("cvt.rna.tf32.f32 %0, %1;" : "=r"(u) : "f"(f)); return u;
}
__device__ __forceinline__ uint4 f2tf4(float4 v) {
    return make_uint4(f2tf(v.x), f2tf(v.y), f2tf(v.z), f2tf(v.w));
}
// pack: lo -> lower 16 bits, hi -> upper 16 bits
__device__ __forceinline__ unsigned packbf(float lo, float hi) {
    unsigned u; asm("cvt.rn.bf16x2.f32 %0, %1, %2;" : "=r"(u) : "f"(hi), "f"(lo)); return u;
}
__device__ __forceinline__ float bf_lo(unsigned u) { return __uint_as_float(u << 16); }
__device__ __forceinline__ float bf_hi(unsigned u) { return __uint_as_float(u & 0xffff0000u); }
__device__ __forceinline__ void mma8(float d[4], const unsigned a[4], const unsigned b[2]) {
    asm volatile(
        "mma.sync.aligned.m16n8k8.row.col.f32.tf32.tf32.f32 "
        "{%0,%1,%2,%3},{%4,%5,%6,%7},{%8,%9},{%0,%1,%2,%3};"
        : "+f"(d[0]), "+f"(d[1]), "+f"(d[2]), "+f"(d[3])
        : "r"(a[0]), "r"(a[1]), "r"(a[2]), "r"(a[3]), "r"(b[0]), "r"(b[1]));
}
__device__ __forceinline__ void mma16b(float d[4], const unsigned a[4], const unsigned b[2]) {
    asm volatile(
        "mma.sync.aligned.m16n8k16.row.col.f32.bf16.bf16.f32 "
        "{%0,%1,%2,%3},{%4,%5,%6,%7},{%8,%9},{%0,%1,%2,%3};"
        : "+f"(d[0]), "+f"(d[1]), "+f"(d[2]), "+f"(d[3])
        : "r"(a[0]), "r"(a[1]), "r"(a[2]), "r"(a[3]), "r"(b[0]), "r"(b[1]));
}

// ---------------- kernel 0: weight transpose  srw[o][c][kh][kw] -> g_wt[o][kg=tap*64+c]
__global__ void __launch_bounds__(256) k_transpose(const float* __restrict__ srw) {
    int base = blockIdx.x * 256 + threadIdx.x;
#pragma unroll
    for (int it = 0; it < 4; it++) {
        int i = base + it * 65536;
        int o   = i >> 12;
        int kg  = i & 4095;
        int tap = kg >> 6, c = kg & 63;
        int kh = tap >> 3, kw = tap & 7;
        g_wt[i] = srw[((o * 64 + c) * 8 + kh) * 8 + kw];
    }
}

// ---------------- kernel 1: SR conv as split-K implicit GEMM (tf32 mma) ----------------
__global__ void __launch_bounds__(256) k_conv(const float* __restrict__ x) {
    __shared__ unsigned As[64 * 20];
    __shared__ unsigned Bsm[64 * 20];
    int tid = threadIdx.x, w = tid >> 5, ln = tid & 31;
    int lr = ln >> 2, lc = ln & 3;
    int mtile = blockIdx.x, ks = blockIdx.y;
    int mt = w & 3, nq = w >> 2;
    float acc[4][4] = {};

    int lm = tid >> 2, lkq = tid & 3;
    int gm = mtile * 64 + lm;
    int bb = gm >> 8, pos = gm & 255;
    int oh = pos >> 4, ow = pos & 15;

    for (int kc = 0; kc < 256; kc += 16) {
        int kg  = ks * 256 + kc + lkq * 4;
        int tap = kg >> 6, c = kg & 63;
        int kh = tap >> 3, kw = tap & 7;
        int pix = (oh * 8 + kh) * 128 + (ow * 8 + kw);
        *(uint4*)&As[lm * 20 + lkq * 4] =
            f2tf4(*(const float4*)&x[(bb * NN + pix) * 64 + c]);
        *(uint4*)&Bsm[lm * 20 + lkq * 4] =
            f2tf4(*(const float4*)&g_wt[lm * 4096 + ks * 256 + kc + lkq * 4]);
        __syncthreads();
#pragma unroll
        for (int kb = 0; kb < 16; kb += 8) {
            const unsigned* ab = &As[(mt * 16 + lr) * 20 + kb + lc];
            unsigned af[4] = {ab[0], ab[8 * 20], ab[4], ab[8 * 20 + 4]};
#pragma unroll
            for (int nt = 0; nt < 4; nt++) {
                const unsigned* bp = &Bsm[(nq * 32 + nt * 8 + lr) * 20 + kb + lc];
                unsigned bf[2] = {bp[0], bp[4]};
                mma8(acc[nt], af, bf);
            }
        }
        __syncthreads();
    }
    float* outp = &g_part[ks * 65536 + (mtile * 64) * 64];
#pragma unroll
    for (int nt = 0; nt < 4; nt++) {
        int r = mt * 16 + lr, c0 = nq * 32 + nt * 8 + 2 * lc;
        *(float2*)&outp[r * 64 + c0]       = make_float2(acc[nt][0], acc[nt][1]);
        *(float2*)&outp[(r + 8) * 64 + c0] = make_float2(acc[nt][2], acc[nt][3]);
    }
}

// ---------------- kernel 2: reduce partials -> LN -> kv proj -> precomputed formats ----
// grid 512: block handles m-pair (2*bid, 2*bid+1) so V pairs pack in-block.
__global__ void __launch_bounds__(256) k_lnkv(
    const float* __restrict__ srb, const float* __restrict__ lng,
    const float* __restrict__ lnb, const float* __restrict__ kvw,
    const float* __restrict__ kvb)
{
    __shared__ float snx[2][64];
    __shared__ float red[2][2][2];
    __shared__ float vsm[2][64];
    int tid = threadIdx.x, sub = tid >> 7, t = tid & 127;
    int m = blockIdx.x * 2 + sub;
    float v = 0.f;
    if (t < 64) {
        v = srb[t];
#pragma unroll
        for (int s = 0; s < 16; s++) v += g_part[s * 65536 + m * 64 + t];
        float sv = v, sq = v * v;
#pragma unroll
        for (int off = 16; off; off >>= 1) {
            sv += __shfl_xor_sync(0xffffffffu, sv, off);
            sq += __shfl_xor_sync(0xffffffffu, sq, off);
        }
        if ((t & 31) == 0) { red[sub][t >> 5][0] = sv; red[sub][t >> 5][1] = sq; }
    }
    __syncthreads();
    float mu  = (red[sub][0][0] + red[sub][1][0]) * (1.f / 64.f);
    float var = (red[sub][0][1] + red[sub][1][1]) * (1.f / 64.f) - mu * mu;
    float rstd = rsqrtf(var + 1e-5f);
    if (t < 64) snx[sub][t] = (v - mu) * rstd * lng[t] + lnb[t];
    __syncthreads();

    int o = t;
    float acc = kvb[o];
#pragma unroll
    for (int c4 = 0; c4 < 16; c4++) {
        float4 ww = *(const float4*)&kvw[o * 64 + c4 * 4];
        acc += snx[sub][c4 * 4 + 0] * ww.x + snx[sub][c4 * 4 + 1] * ww.y
             + snx[sub][c4 * 4 + 2] * ww.z + snx[sub][c4 * 4 + 3] * ww.w;
    }
    int bb = m >> 8, mm = m & 255;
    if (o < 64) {           // K -> tf32
        int h = o >> 5, d = o & 31;
        g_ktf[((bb * 2 + h) * 256 + mm) * 32 + d] = f2tf(acc);
    } else {                // V -> stash for pair packing
        vsm[sub][o - 64] = acc;
    }
    __syncthreads();
    if (tid < 64) {
        int h = tid >> 5, d = tid & 31;
        float v0 = vsm[0][tid], v1 = vsm[1][tid];
        unsigned hi = packbf(v0, v1);
        unsigned lo = packbf(v0 - bf_lo(hi), v1 - bf_hi(hi));
        int bb2 = blockIdx.x >> 7, k2 = blockIdx.x & 127;
        int idx = ((bb2 * 2 + h) * 128 + k2) * 32 + d;
        g_vhi[idx] = hi;
        g_vlo[idx] = lo;
    }
}

// ---------------- kernel 3: fused attention, 64-row tiles, pure-copy staging ----------
// smem layout (4-byte words):
#define SQ    0        // q tf32 [r*68 + h*32+d], scale folded          (4352)
#define SOB   4352     // qw tf32 at start; attn-out tf32 [r*68+c]      (4352)
#define SK    8704     // K tf32 head [m*36+d]; pw tf32 [o*68+c] at end (9216)
#define SVH   17920    // V bf16-hi packed [k2*40 + n]                  (5120)
#define SVL   23040    // V bf16-lo packed [k2*40 + n]                  (5120)
#define SRED  28160    // x-tile tf32 at start; attn@V partials [nh][64][34] (8704)
#define SROW  36864    // row max/sum [64][8]                           (512)
#define SMFW  37376    // words -> 149504 bytes

__global__ void __launch_bounds__(512, 1) k_attn(
    const float* __restrict__ x,  const float* __restrict__ pos,
    const float* __restrict__ qw, const float* __restrict__ qb,
    const float* __restrict__ pw, const float* __restrict__ pb,
    const float* __restrict__ alpha, float* __restrict__ out)
{
    extern __shared__ float sm[];
    unsigned* smU = (unsigned*)sm;
    int tid = threadIdx.x, w = tid >> 5, ln = tid & 31;
    int lr = ln >> 2, lc = ln & 3;
    int b = blockIdx.y;
    int n0 = blockIdx.x * 64;
    float a_ = __ldg(alpha);

    // x tile -> SRED (tf32, stride 68), qw -> SOB (tf32)
#pragma unroll
    for (int it = 0; it < 2; it++) {
        int lin = it * 512 + tid;
        int r = lin >> 4, c4 = (lin & 15) * 4;
        *(uint4*)&smU[SRED + r * 68 + c4] =
            f2tf4(*(const float4*)&x[((size_t)b * NN + n0 + r) * 64 + c4]);
        *(uint4*)&smU[SOB + r * 68 + c4] =
            f2tf4(*(const float4*)&qw[r * 64 + c4]);
    }
    __syncthreads();

    // ---- q-proj: SQ = x @ qw^T (scale folded) ----
    {
        int mt = w >> 2, nq = w & 3;
        float acc[2][4] = {};
#pragma unroll
        for (int ks = 0; ks < 8; ks++) {
            const unsigned* ab = &smU[SRED + (mt * 16 + lr) * 68 + ks * 8 + lc];
            unsigned af[4] = {ab[0], ab[8 * 68], ab[4], ab[8 * 68 + 4]};
#pragma unroll
            for (int nt = 0; nt < 2; nt++) {
                const unsigned* bp = &smU[SOB + (nq * 16 + nt * 8 + lr) * 68 + ks * 8 + lc];
                unsigned bf[2] = {bp[0], bp[4]};
                mma8(acc[nt], af, bf);
            }
        }
#pragma unroll
        for (int nt = 0; nt < 2; nt++) {
            int c0 = nq * 16 + nt * 8 + 2 * lc;
            int r = mt * 16 + lr;
            float b0 = __ldg(&qb[c0]), b1 = __ldg(&qb[c0 + 1]);
            smU[SQ + r * 68 + c0]           = f2tf((acc[nt][0] + b0) * QK_SCALE);
            smU[SQ + r * 68 + c0 + 1]       = f2tf((acc[nt][1] + b1) * QK_SCALE);
            smU[SQ + (r + 8) * 68 + c0]     = f2tf((acc[nt][2] + b0) * QK_SCALE);
            smU[SQ + (r + 8) * 68 + c0 + 1] = f2tf((acc[nt][3] + b1) * QK_SCALE);
        }
    }
    __syncthreads();

    int mt = w & 3, nh = w >> 2;            // logits/attn decomposition
    int rowA = mt * 16 + lr;

    for (int h = 0; h < 2; h++) {
        int b2h = b * 2 + h;
        // stage K (tf32, stride 36) and V planes (stride 40) — pure uint4 copies
#pragma unroll
        for (int it = 0; it < 4; it++) {
            int lin = it * 512 + tid;           // 2048 uint4
            int m = lin >> 3, d4 = (lin & 7) * 4;
            *(uint4*)&smU[SK + m * 36 + d4] =
                *(const uint4*)&g_ktf[(b2h * 256 + m) * 32 + d4];
        }
#pragma unroll
        for (int it = 0; it < 2; it++) {
            int lin = it * 512 + tid;           // 1024 uint4 per plane
            int k2 = lin >> 3, n4 = (lin & 7) * 4;
            *(uint4*)&smU[SVH + k2 * 40 + n4] =
                *(const uint4*)&g_vhi[(b2h * 128 + k2) * 32 + n4];
            *(uint4*)&smU[SVL + k2 * 40 + n4] =
                *(const uint4*)&g_vlo[(b2h * 128 + k2) * 32 + n4];
        }
        __syncthreads();

        // ---- logits for rows [mt*16..+15], cols [nh*64..+63] (in registers) ----
        float acc[8][4];
#pragma unroll
        for (int i = 0; i < 8; i++)
            acc[i][0] = acc[i][1] = acc[i][2] = acc[i][3] = 0.f;
#pragma unroll
        for (int ks = 0; ks < 4; ks++) {
            const unsigned* ab = &smU[SQ + rowA * 68 + h * 32 + ks * 8 + lc];
            unsigned af[4] = {ab[0], ab[8 * 68], ab[4], ab[8 * 68 + 4]};
#pragma unroll
            for (int nt = 0; nt < 8; nt++) {
                const unsigned* bp = &smU[SK + (nh * 64 + nt * 8 + lr) * 36 + ks * 8 + lc];
                unsigned bf[2] = {bp[0], bp[4]};
                mma8(acc[nt], af, bf);
            }
        }

        // ---- softmax (register + tiny smem cross-warp exchange) ----
        float mx0 = -1e30f, mx1 = -1e30f;
#pragma unroll
        for (int nt = 0; nt < 8; nt++) {
            mx0 = fmaxf(mx0, fmaxf(acc[nt][0], acc[nt][1]));
            mx1 = fmaxf(mx1, fmaxf(acc[nt][2], acc[nt][3]));
        }
        mx0 = fmaxf(mx0, __shfl_xor_sync(0xffffffffu, mx0, 1));
        mx0 = fmaxf(mx0, __shfl_xor_sync(0xffffffffu, mx0, 2));
        mx1 = fmaxf(mx1, __shfl_xor_sync(0xffffffffu, mx1, 1));
        mx1 = fmaxf(mx1, __shfl_xor_sync(0xffffffffu, mx1, 2));
        if (lc == 0) {
            sm[SROW + rowA * 8 + nh]       = mx0;
            sm[SROW + (rowA + 8) * 8 + nh] = mx1;
        }
        __syncthreads();
        float4 m40 = *(float4*)&sm[SROW + rowA * 8];
        float4 m41 = *(float4*)&sm[SROW + (rowA + 8) * 8];
        float gm0 = fmaxf(fmaxf(m40.x, m40.y), fmaxf(m40.z, m40.w));
        float gm1 = fmaxf(fmaxf(m41.x, m41.y), fmaxf(m41.z, m41.w));
        float s0 = 0.f, s1 = 0.f;
#pragma unroll
        for (int nt = 0; nt < 8; nt++) {
            acc[nt][0] = __expf(acc[nt][0] - gm0); s0 += acc[nt][0];
            acc[nt][1] = __expf(acc[nt][1] - gm0); s0 += acc[nt][1];
            acc[nt][2] = __expf(acc[nt][2] - gm1); s1 += acc[nt][2];
            acc[nt][3] = __expf(acc[nt][3] - gm1); s1 += acc[nt][3];
        }
        s0 += __shfl_xor_sync(0xffffffffu, s0, 1);
        s0 += __shfl_xor_sync(0xffffffffu, s0, 2);
        s1 += __shfl_xor_sync(0xffffffffu, s1, 1);
        s1 += __shfl_xor_sync(0xffffffffu, s1, 2);
        if (lc == 0) {
            sm[SROW + rowA * 8 + 4 + nh]       = s0;
            sm[SROW + (rowA + 8) * 8 + 4 + nh] = s1;
        }
        __syncthreads();
        float4 s40 = *(float4*)&sm[SROW + rowA * 8 + 4];
        float4 s41 = *(float4*)&sm[SROW + (rowA + 8) * 8 + 4];
        float inv0 = (1.f - a_) / (s40.x + s40.y + s40.z + s40.w);
        float inv1 = (1.f - a_) / (s41.x + s41.y + s41.z + s41.w);

        // ---- blend + split-bf16 pack + attn@V partial (k-range nh*64..+63) ----
        const float* pr0 = &pos[((size_t)b2h * NN + n0 + rowA) * 256];
        const float* pr1 = pr0 + 8 * 256;
        float accO[4][4];
#pragma unroll
        for (int i = 0; i < 4; i++)
            accO[i][0] = accO[i][1] = accO[i][2] = accO[i][3] = 0.f;
#pragma unroll
        for (int kk = 0; kk < 4; kk++) {
            unsigned afh[4], afl[4];
#pragma unroll
            for (int q = 0; q < 2; q++) {
                int nt = 2 * kk + q;
                int cb = nh * 64 + nt * 8 + 2 * lc;
                float2 p0 = __ldg((const float2*)&pr0[cb]);
                float2 p1 = __ldg((const float2*)&pr1[cb]);
                float w00 = acc[nt][0] * inv0 + a_ * p0.x;
                float w01 = acc[nt][1] * inv0 + a_ * p0.y;
                float w10 = acc[nt][2] * inv1 + a_ * p1.x;
                float w11 = acc[nt][3] * inv1 + a_ * p1.y;
                unsigned h0 = packbf(w00, w01);
                unsigned h1 = packbf(w10, w11);
                afh[2 * q]     = h0;
                afh[2 * q + 1] = h1;
                afl[2 * q]     = packbf(w00 - bf_lo(h0), w01 - bf_hi(h0));
                afl[2 * q + 1] = packbf(w10 - bf_lo(h1), w11 - bf_hi(h1));
            }
            int k2b = nh * 32 + kk * 8;
#pragma unroll
            for (int ntv = 0; ntv < 4; ntv++) {
                const unsigned* bph = &smU[SVH + (k2b + lc) * 40 + ntv * 8 + lr];
                const unsigned* bpl = &smU[SVL + (k2b + lc) * 40 + ntv * 8 + lr];
                unsigned bh[2] = {bph[0], bph[4 * 40]};
                unsigned bl[2] = {bpl[0], bpl[4 * 40]};
                mma16b(accO[ntv], afh, bh);
                mma16b(accO[ntv], afh, bl);
                mma16b(accO[ntv], afl, bh);
            }
        }
        // write partials [nh][row][col]
#pragma unroll
        for (int ntv = 0; ntv < 4; ntv++) {
            int cc = ntv * 8 + 2 * lc;
            *(float2*)&sm[SRED + nh * 2176 + rowA * 34 + cc] =
                make_float2(accO[ntv][0], accO[ntv][1]);
            *(float2*)&sm[SRED + nh * 2176 + (rowA + 8) * 34 + cc] =
                make_float2(accO[ntv][2], accO[ntv][3]);
        }
        __syncthreads();
        // reduce 4 partials -> SOB (tf32)
#pragma unroll
        for (int i = 0; i < 2; i++) {
            int p = i * 512 + tid;
            int r = p >> 4, c2 = (p & 15) * 2;
            float sx = 0.f, sy = 0.f;
#pragma unroll
            for (int g = 0; g < 4; g++) {
                float2 t = *(float2*)&sm[SRED + g * 2176 + r * 34 + c2];
                sx += t.x; sy += t.y;
            }
            smU[SOB + r * 68 + h * 32 + c2]     = f2tf(sx);
            smU[SOB + r * 68 + h * 32 + c2 + 1] = f2tf(sy);
        }
        __syncthreads();
    }

    // pw -> SK region (tf32, stride 68)
#pragma unroll
    for (int it = 0; it < 2; it++) {
        int lin = it * 512 + tid;
        int r = lin >> 4, c4 = (lin & 15) * 4;
        *(uint4*)&smU[SK + r * 68 + c4] = f2tf4(*(const float4*)&pw[r * 64 + c4]);
    }
    __syncthreads();

    // ---- out-proj: out = attn_out @ pw^T + pb (direct STG) ----
    {
        int mtp = w >> 2, nq = w & 3;
        float acc[2][4] = {};
#pragma unroll
        for (int ks = 0; ks < 8; ks++) {
            const unsigned* ab = &smU[SOB + (mtp * 16 + lr) * 68 + ks * 8 + lc];
            unsigned af[4] = {ab[0], ab[8 * 68], ab[4], ab[8 * 68 + 4]};
#pragma unroll
            for (int nt = 0; nt < 2; nt++) {
                const unsigned* bp = &smU[SK + (nq * 16 + nt * 8 + lr) * 68 + ks * 8 + lc];
                unsigned bf[2] = {bp[0], bp[4]};
                mma8(acc[nt], af, bf);
            }
        }
#pragma unroll
        for (int nt = 0; nt < 2; nt++) {
            int c0 = nq * 16 + nt * 8 + 2 * lc;
            int r = mtp * 16 + lr;
            float b0 = __ldg(&pb[c0]), b1 = __ldg(&pb[c0 + 1]);
            *(float2*)&out[((size_t)b * NN + n0 + r) * 64 + c0] =
                make_float2(acc[nt][0] + b0, acc[nt][1] + b1);
            *(float2*)&out[((size_t)b * NN + n0 + r + 8) * 64 + c0] =
                make_float2(acc[nt][2] + b0, acc[nt][3] + b1);
        }
    }
}

// ---------------- launch ----------------
extern "C" void kernel_launch(void* const* d_in, const int* in_sizes, int n_in,
                              void* d_out, int out_size) {
    const float* x     = (const float*)d_in[0];
    const float* pos   = (const float*)d_in[1];
    const float* qw    = (const float*)d_in[2];
    const float* qb    = (const float*)d_in[3];
    const float* kvw   = (const float*)d_in[4];
    const float* kvb   = (const float*)d_in[5];
    const float* pw    = (const float*)d_in[6];
    const float* pb    = (const float*)d_in[7];
    const float* srw   = (const float*)d_in[8];
    const float* srb   = (const float*)d_in[9];
    const float* lng   = (const float*)d_in[10];
    const float* lnb   = (const float*)d_in[11];
    const float* alpha = (const float*)d_in[12];
    float* out = (float*)d_out;

    cudaFuncSetAttribute(k_attn, cudaFuncAttributeMaxDynamicSharedMemorySize,
                         SMFW * 4);

    k_transpose<<<256, 256>>>(srw);
    k_conv<<<dim3(16, 16), 256>>>(x);
    k_lnkv<<<512, 256>>>(srb, lng, lnb, kvw, kvb);
    k_attn<<<dim3(256, 4), 512, SMFW * 4>>>(x, pos, qw, qb, pw, pb, alpha, out);
}

// round 11
// speedup vs baseline: 4.3055x; 1.1059x over previous
#include <cuda_runtime.h>
#include <math.h>

// Problem constants
#define BB   4
#define NN   16384
#define QK_SCALE 0.17677669529663687f   // 32^-0.5

// ---------------- scratch (device globals; no allocation) ----------------
__device__ float    g_wt[64 * 4096];         // conv weights transposed [o][k]
__device__ float    g_part[16 * 1024 * 64];  // conv split-K partials
__device__ unsigned g_ktf[8 * 256 * 32];     // K tf32 [b*2+h][m][d]
__device__ unsigned g_vhi[8 * 128 * 32];     // V bf16-hi pairs [b*2+h][k2][n]
__device__ unsigned g_vlo[8 * 128 * 32];     // V bf16-lo pairs [b*2+h][k2][n]

// ---------------- helpers ----------------
__device__ __forceinline__ unsigned f2tf(float f) {
    unsigned u; asm("cvt.rna.tf32.f32 %0, %1;" : "=r"(u) : "f"(f)); return u;
}
__device__ __forceinline__ uint4 f2tf4(float4 v) {
    return make_uint4(f2tf(v.x), f2tf(v.y), f2tf(v.z), f2tf(v.w));
}
__device__ __forceinline__ unsigned packbf(float lo, float hi) {
    unsigned u; asm("cvt.rn.bf16x2.f32 %0, %1, %2;" : "=r"(u) : "f"(hi), "f"(lo)); return u;
}
__device__ __forceinline__ float bf_lo(unsigned u) { return __uint_as_float(u << 16); }
__device__ __forceinline__ float bf_hi(unsigned u) { return __uint_as_float(u & 0xffff0000u); }
__device__ __forceinline__ void mma8(float d[4], const unsigned a[4], const unsigned b[2]) {
    asm volatile(
        "mma.sync.aligned.m16n8k8.row.col.f32.tf32.tf32.f32 "
        "{%0,%1,%2,%3},{%4,%5,%6,%7},{%8,%9},{%0,%1,%2,%3};"
        : "+f"(d[0]), "+f"(d[1]), "+f"(d[2]), "+f"(d[3])
        : "r"(a[0]), "r"(a[1]), "r"(a[2]), "r"(a[3]), "r"(b[0]), "r"(b[1]));
}
__device__ __forceinline__ void mma16b(float d[4], const unsigned a[4], const unsigned b[2]) {
    asm volatile(
        "mma.sync.aligned.m16n8k16.row.col.f32.bf16.bf16.f32 "
        "{%0,%1,%2,%3},{%4,%5,%6,%7},{%8,%9},{%0,%1,%2,%3};"
        : "+f"(d[0]), "+f"(d[1]), "+f"(d[2]), "+f"(d[3])
        : "r"(a[0]), "r"(a[1]), "r"(a[2]), "r"(a[3]), "r"(b[0]), "r"(b[1]));
}
__device__ __forceinline__ void cpa16(unsigned dst, const void* src) {
    asm volatile("cp.async.cg.shared.global [%0], [%1], 16;" :: "r"(dst), "l"(src));
}
#define CP_COMMIT() asm volatile("cp.async.commit_group;")
#define CP_WAIT(n)  asm volatile("cp.async.wait_group %0;" :: "n"(n))

// ---------------- kernel 0: weight transpose ----------------
__global__ void __launch_bounds__(256) k_transpose(const float* __restrict__ srw) {
    int base = blockIdx.x * 256 + threadIdx.x;
#pragma unroll
    for (int it = 0; it < 4; it++) {
        int i = base + it * 65536;
        int o   = i >> 12;
        int kg  = i & 4095;
        int tap = kg >> 6, c = kg & 63;
        int kh = tap >> 3, kw = tap & 7;
        g_wt[i] = srw[((o * 64 + c) * 8 + kh) * 8 + kw];
    }
}

// ---------------- kernel 1: SR conv as split-K implicit GEMM (tf32 mma) ----------------
__global__ void __launch_bounds__(256) k_conv(const float* __restrict__ x) {
    __shared__ unsigned As[64 * 20];
    __shared__ unsigned Bsm[64 * 20];
    int tid = threadIdx.x, w = tid >> 5, ln = tid & 31;
    int lr = ln >> 2, lc = ln & 3;
    int mtile = blockIdx.x, ks = blockIdx.y;
    int mt = w & 3, nq = w >> 2;
    float acc[4][4] = {};

    int lm = tid >> 2, lkq = tid & 3;
    int gm = mtile * 64 + lm;
    int bb = gm >> 8, pos = gm & 255;
    int oh = pos >> 4, ow = pos & 15;

    for (int kc = 0; kc < 256; kc += 16) {
        int kg  = ks * 256 + kc + lkq * 4;
        int tap = kg >> 6, c = kg & 63;
        int kh = tap >> 3, kw = tap & 7;
        int pix = (oh * 8 + kh) * 128 + (ow * 8 + kw);
        *(uint4*)&As[lm * 20 + lkq * 4] =
            f2tf4(*(const float4*)&x[(bb * NN + pix) * 64 + c]);
        *(uint4*)&Bsm[lm * 20 + lkq * 4] =
            f2tf4(*(const float4*)&g_wt[lm * 4096 + ks * 256 + kc + lkq * 4]);
        __syncthreads();
#pragma unroll
        for (int kb = 0; kb < 16; kb += 8) {
            const unsigned* ab = &As[(mt * 16 + lr) * 20 + kb + lc];
            unsigned af[4] = {ab[0], ab[8 * 20], ab[4], ab[8 * 20 + 4]};
#pragma unroll
            for (int nt = 0; nt < 4; nt++) {
                const unsigned* bp = &Bsm[(nq * 32 + nt * 8 + lr) * 20 + kb + lc];
                unsigned bf[2] = {bp[0], bp[4]};
                mma8(acc[nt], af, bf);
            }
        }
        __syncthreads();
    }
    float* outp = &g_part[ks * 65536 + (mtile * 64) * 64];
#pragma unroll
    for (int nt = 0; nt < 4; nt++) {
        int r = mt * 16 + lr, c0 = nq * 32 + nt * 8 + 2 * lc;
        *(float2*)&outp[r * 64 + c0]       = make_float2(acc[nt][0], acc[nt][1]);
        *(float2*)&outp[(r + 8) * 64 + c0] = make_float2(acc[nt][2], acc[nt][3]);
    }
}

// ---------------- kernel 2: reduce partials -> LN -> kv proj -> precomputed formats ----
__global__ void __launch_bounds__(256) k_lnkv(
    const float* __restrict__ srb, const float* __restrict__ lng,
    const float* __restrict__ lnb, const float* __restrict__ kvw,
    const float* __restrict__ kvb)
{
    __shared__ float snx[2][64];
    __shared__ float red[2][2][2];
    __shared__ float vsm[2][64];
    int tid = threadIdx.x, sub = tid >> 7, t = tid & 127;
    int m = blockIdx.x * 2 + sub;
    float v = 0.f;
    if (t < 64) {
        v = srb[t];
#pragma unroll
        for (int s = 0; s < 16; s++) v += g_part[s * 65536 + m * 64 + t];
        float sv = v, sq = v * v;
#pragma unroll
        for (int off = 16; off; off >>= 1) {
            sv += __shfl_xor_sync(0xffffffffu, sv, off);
            sq += __shfl_xor_sync(0xffffffffu, sq, off);
        }
        if ((t & 31) == 0) { red[sub][t >> 5][0] = sv; red[sub][t >> 5][1] = sq; }
    }
    __syncthreads();
    float mu  = (red[sub][0][0] + red[sub][1][0]) * (1.f / 64.f);
    float var = (red[sub][0][1] + red[sub][1][1]) * (1.f / 64.f) - mu * mu;
    float rstd = rsqrtf(var + 1e-5f);
    if (t < 64) snx[sub][t] = (v - mu) * rstd * lng[t] + lnb[t];
    __syncthreads();

    int o = t;
    float acc = kvb[o];
#pragma unroll
    for (int c4 = 0; c4 < 16; c4++) {
        float4 ww = *(const float4*)&kvw[o * 64 + c4 * 4];
        acc += snx[sub][c4 * 4 + 0] * ww.x + snx[sub][c4 * 4 + 1] * ww.y
             + snx[sub][c4 * 4 + 2] * ww.z + snx[sub][c4 * 4 + 3] * ww.w;
    }
    int bb = m >> 8, mm = m & 255;
    if (o < 64) {
        int h = o >> 5, d = o & 31;
        g_ktf[((bb * 2 + h) * 256 + mm) * 32 + d] = f2tf(acc);
    } else {
        vsm[sub][o - 64] = acc;
    }
    __syncthreads();
    if (tid < 64) {
        int h = tid >> 5, d = tid & 31;
        float v0 = vsm[0][tid], v1 = vsm[1][tid];
        unsigned hi = packbf(v0, v1);
        unsigned lo = packbf(v0 - bf_lo(hi), v1 - bf_hi(hi));
        int bb2 = blockIdx.x >> 7, k2 = blockIdx.x & 127;
        int idx = ((bb2 * 2 + h) * 128 + k2) * 32 + d;
        g_vhi[idx] = hi;
        g_vlo[idx] = lo;
    }
}

// ---------------- kernel 3: fused attention, cp.async pipelined ----------
// smem layout (4-byte words):
#define SQ    0        // q tf32 [r*68 + h*32+d], scale folded          (4352)
#define SOB   4352     // qw tf32 at start; attn-out tf32 [r*68+c]      (4352)
#define SK    8704     // K tf32 head [m*36+d]; pw tf32 [o*68+c] at end (9216)
#define SVH   17920    // V bf16-hi packed [k2*40 + n]                  (5120)
#define SVL   23040    // V bf16-lo packed [k2*40 + n]                  (5120)
#define SRED  28160    // x-tile tf32 at start; attn@V partials [nh][64][34] (8704)
#define SROW  36864    // row sums [64][4]                              (256)
#define SPOS  37120    // pos tile f32 [64][260]                        (16640)
#define SMFW  53760    // words -> 215040 bytes

__global__ void __launch_bounds__(512, 1) k_attn(
    const float* __restrict__ x,  const float* __restrict__ pos,
    const float* __restrict__ qw, const float* __restrict__ qb,
    const float* __restrict__ pw, const float* __restrict__ pb,
    const float* __restrict__ alpha, float* __restrict__ out)
{
    extern __shared__ float sm[];
    unsigned* smU = (unsigned*)sm;
    unsigned smb = (unsigned)__cvta_generic_to_shared(sm);
    int tid = threadIdx.x, w = tid >> 5, ln = tid & 31;
    int lr = ln >> 2, lc = ln & 3;
    int b = blockIdx.y;
    int n0 = blockIdx.x * 64;
    float a_ = __ldg(alpha);

    int mt = w & 3, nh = w >> 2;            // logits/attn decomposition
    int rowA = mt * 16 + lr;

    // ---- G1: cp.async K+V for h=0 ----
    {
        int b2h = b * 2;
#pragma unroll
        for (int it = 0; it < 4; it++) {
            int lin = it * 512 + tid;
            int m = lin >> 3, d4 = (lin & 7) * 4;
            cpa16(smb + (SK + m * 36 + d4) * 4, &g_ktf[(b2h * 256 + m) * 32 + d4]);
        }
#pragma unroll
        for (int it = 0; it < 2; it++) {
            int lin = it * 512 + tid;
            int k2 = lin >> 3, n4 = (lin & 7) * 4;
            cpa16(smb + (SVH + k2 * 40 + n4) * 4, &g_vhi[(b2h * 128 + k2) * 32 + n4]);
            cpa16(smb + (SVL + k2 * 40 + n4) * 4, &g_vlo[(b2h * 128 + k2) * 32 + n4]);
        }
        CP_COMMIT();
    }
    // ---- G2: cp.async pos slice for h=0 (warp-private 16x64 tile) ----
    {
        int b2h = b * 2;
#pragma unroll
        for (int i = 0; i < 8; i++) {
            int q = ln + 32 * i;
            int r = q >> 4, ch = q & 15;
            cpa16(smb + (SPOS + (mt * 16 + r) * 260 + nh * 64 + ch * 4) * 4,
                  &pos[((size_t)b2h * NN + n0 + mt * 16 + r) * 256 + nh * 64 + ch * 4]);
        }
        CP_COMMIT();
    }

    // x tile -> SRED (tf32, stride 68), qw -> SOB (tf32)
#pragma unroll
    for (int it = 0; it < 2; it++) {
        int lin = it * 512 + tid;
        int r = lin >> 4, c4 = (lin & 15) * 4;
        *(uint4*)&smU[SRED + r * 68 + c4] =
            f2tf4(*(const float4*)&x[((size_t)b * NN + n0 + r) * 64 + c4]);
        *(uint4*)&smU[SOB + r * 68 + c4] =
            f2tf4(*(const float4*)&qw[r * 64 + c4]);
    }
    __syncthreads();

    // ---- q-proj: SQ = x @ qw^T (scale folded) ----
    {
        int mtp = w >> 2, nq = w & 3;
        float acc[2][4] = {};
#pragma unroll
        for (int ks = 0; ks < 8; ks++) {
            const unsigned* ab = &smU[SRED + (mtp * 16 + lr) * 68 + ks * 8 + lc];
            unsigned af[4] = {ab[0], ab[8 * 68], ab[4], ab[8 * 68 + 4]};
#pragma unroll
            for (int nt = 0; nt < 2; nt++) {
                const unsigned* bp = &smU[SOB + (nq * 16 + nt * 8 + lr) * 68 + ks * 8 + lc];
                unsigned bf[2] = {bp[0], bp[4]};
                mma8(acc[nt], af, bf);
            }
        }
#pragma unroll
        for (int nt = 0; nt < 2; nt++) {
            int c0 = nq * 16 + nt * 8 + 2 * lc;
            int r = mtp * 16 + lr;
            float b0 = __ldg(&qb[c0]), b1 = __ldg(&qb[c0 + 1]);
            smU[SQ + r * 68 + c0]           = f2tf((acc[nt][0] + b0) * QK_SCALE);
            smU[SQ + r * 68 + c0 + 1]       = f2tf((acc[nt][1] + b1) * QK_SCALE);
            smU[SQ + (r + 8) * 68 + c0]     = f2tf((acc[nt][2] + b0) * QK_SCALE);
            smU[SQ + (r + 8) * 68 + c0 + 1] = f2tf((acc[nt][3] + b1) * QK_SCALE);
        }
    }
    CP_WAIT(1);          // G1 (K/V h=0) complete
    __syncthreads();     // SQ + staged K/V visible

    for (int h = 0; h < 2; h++) {
        int b2h = b * 2 + h;

        // ---- logits rows [mt*16..+15], cols [nh*64..+63] (registers) ----
        float acc[8][4];
#pragma unroll
        for (int i = 0; i < 8; i++)
            acc[i][0] = acc[i][1] = acc[i][2] = acc[i][3] = 0.f;
#pragma unroll
        for (int ks = 0; ks < 4; ks++) {
            const unsigned* ab = &smU[SQ + rowA * 68 + h * 32 + ks * 8 + lc];
            unsigned af[4] = {ab[0], ab[8 * 68], ab[4], ab[8 * 68 + 4]};
#pragma unroll
            for (int nt = 0; nt < 8; nt++) {
                const unsigned* bp = &smU[SK + (nh * 64 + nt * 8 + lr) * 36 + ks * 8 + lc];
                unsigned bf[2] = {bp[0], bp[4]};
                mma8(acc[nt], af, bf);
            }
        }

        // ---- exp (logits are O(1): no max pass needed) + sum exchange ----
        float s0 = 0.f, s1 = 0.f;
#pragma unroll
        for (int nt = 0; nt < 8; nt++) {
            acc[nt][0] = __expf(acc[nt][0]); s0 += acc[nt][0];
            acc[nt][1] = __expf(acc[nt][1]); s0 += acc[nt][1];
            acc[nt][2] = __expf(acc[nt][2]); s1 += acc[nt][2];
            acc[nt][3] = __expf(acc[nt][3]); s1 += acc[nt][3];
        }
        s0 += __shfl_xor_sync(0xffffffffu, s0, 1);
        s0 += __shfl_xor_sync(0xffffffffu, s0, 2);
        s1 += __shfl_xor_sync(0xffffffffu, s1, 1);
        s1 += __shfl_xor_sync(0xffffffffu, s1, 2);
        if (lc == 0) {
            sm[SROW + rowA * 4 + nh]       = s0;
            sm[SROW + (rowA + 8) * 4 + nh] = s1;
        }
        if (h == 1) CP_WAIT(0);   // G4 (pos1) + G5 (V1) complete; barrier publishes
        __syncthreads();          // sums visible; all logits done (SK rewritable)

        if (h == 0) {             // G3: cp.async K for h=1 (overlaps blend+attn@V)
#pragma unroll
            for (int it = 0; it < 4; it++) {
                int lin = it * 512 + tid;
                int m = lin >> 3, d4 = (lin & 7) * 4;
                cpa16(smb + (SK + m * 36 + d4) * 4,
                      &g_ktf[((b2h + 1) * 256 + m) * 32 + d4]);
            }
            CP_COMMIT();
        }

        float4 s40 = *(float4*)&sm[SROW + rowA * 4];
        float4 s41 = *(float4*)&sm[SROW + (rowA + 8) * 4];
        float inv0 = (1.f - a_) / (s40.x + s40.y + s40.z + s40.w);
        float inv1 = (1.f - a_) / (s41.x + s41.y + s41.z + s41.w);

        if (h == 0) {             // pos0 (G2) ready? warp-local wait
            CP_WAIT(1);
            __syncwarp();
        }

        // ---- blend (pos from smem) + split-bf16 pack + attn@V partial ----
        float accO[4][4];
#pragma unroll
        for (int i = 0; i < 4; i++)
            accO[i][0] = accO[i][1] = accO[i][2] = accO[i][3] = 0.f;
#pragma unroll
        for (int kk = 0; kk < 4; kk++) {
            unsigned afh[4], afl[4];
#pragma unroll
            for (int q = 0; q < 2; q++) {
                int nt = 2 * kk + q;
                int cb = nh * 64 + nt * 8 + 2 * lc;
                float2 p0 = *(const float2*)&sm[SPOS + rowA * 260 + cb];
                float2 p1 = *(const float2*)&sm[SPOS + (rowA + 8) * 260 + cb];
                float w00 = acc[nt][0] * inv0 + a_ * p0.x;
                float w01 = acc[nt][1] * inv0 + a_ * p0.y;
                float w10 = acc[nt][2] * inv1 + a_ * p1.x;
                float w11 = acc[nt][3] * inv1 + a_ * p1.y;
                unsigned h0 = packbf(w00, w01);
                unsigned h1 = packbf(w10, w11);
                afh[2 * q]     = h0;
                afh[2 * q + 1] = h1;
                afl[2 * q]     = packbf(w00 - bf_lo(h0), w01 - bf_hi(h0));
                afl[2 * q + 1] = packbf(w10 - bf_lo(h1), w11 - bf_hi(h1));
            }
            int k2b = nh * 32 + kk * 8;
#pragma unroll
            for (int ntv = 0; ntv < 4; ntv++) {
                const unsigned* bph = &smU[SVH + (k2b + lc) * 40 + ntv * 8 + lr];
                const unsigned* bpl = &smU[SVL + (k2b + lc) * 40 + ntv * 8 + lr];
                unsigned bh[2] = {bph[0], bph[4 * 40]};
                unsigned bl[2] = {bpl[0], bpl[4 * 40]};
                mma16b(accO[ntv], afh, bh);
                mma16b(accO[ntv], afh, bl);
                mma16b(accO[ntv], afl, bh);
            }
        }

        if (h == 0) {             // G4: cp.async pos slice for h=1 (own slice read done)
#pragma unroll
            for (int i = 0; i < 8; i++) {
                int q = ln + 32 * i;
                int r = q >> 4, ch = q & 15;
                cpa16(smb + (SPOS + (mt * 16 + r) * 260 + nh * 64 + ch * 4) * 4,
                      &pos[((size_t)(b2h + 1) * NN + n0 + mt * 16 + r) * 256 + nh * 64 + ch * 4]);
            }
            CP_COMMIT();
        }

        // write partials [nh][row][col]
#pragma unroll
        for (int ntv = 0; ntv < 4; ntv++) {
            int cc = ntv * 8 + 2 * lc;
            *(float2*)&sm[SRED + nh * 2176 + rowA * 34 + cc] =
                make_float2(accO[ntv][0], accO[ntv][1]);
            *(float2*)&sm[SRED + nh * 2176 + (rowA + 8) * 34 + cc] =
                make_float2(accO[ntv][2], accO[ntv][3]);
        }
        __syncthreads();          // partials visible; all attn@V done (SV rewritable)

        if (h == 0) {             // G5: cp.async V for h=1 (overlaps reduce)
#pragma unroll
            for (int it = 0; it < 2; it++) {
                int lin = it * 512 + tid;
                int k2 = lin >> 3, n4 = (lin & 7) * 4;
                cpa16(smb + (SVH + k2 * 40 + n4) * 4,
                      &g_vhi[((b2h + 1) * 128 + k2) * 32 + n4]);
                cpa16(smb + (SVL + k2 * 40 + n4) * 4,
                      &g_vlo[((b2h + 1) * 128 + k2) * 32 + n4]);
            }
            CP_COMMIT();
        }

        // reduce 4 partials -> SOB (tf32)
#pragma unroll
        for (int i = 0; i < 2; i++) {
            int p = i * 512 + tid;
            int r = p >> 4, c2 = (p & 15) * 2;
            float sx = 0.f, sy = 0.f;
#pragma unroll
            for (int g = 0; g < 4; g++) {
                float2 t = *(float2*)&sm[SRED + g * 1088 * 2 + r * 34 + c2];
                sx += t.x; sy += t.y;
            }
            smU[SOB + r * 68 + h * 32 + c2]     = f2tf(sx);
            smU[SOB + r * 68 + h * 32 + c2 + 1] = f2tf(sy);
        }
        if (h == 0) CP_WAIT(2);   // G3 (K1) complete; barrier below publishes
        __syncthreads();
    }

    // pw -> SK region (tf32, stride 68)
#pragma unroll
    for (int it = 0; it < 2; it++) {
        int lin = it * 512 + tid;
        int r = lin >> 4, c4 = (lin & 15) * 4;
        *(uint4*)&smU[SK + r * 68 + c4] = f2tf4(*(const float4*)&pw[r * 64 + c4]);
    }
    __syncthreads();

    // ---- out-proj: out = attn_out @ pw^T + pb (direct STG) ----
    {
        int mtp = w >> 2, nq = w & 3;
        float acc[2][4] = {};
#pragma unroll
        for (int ks = 0; ks < 8; ks++) {
            const unsigned* ab = &smU[SOB + (mtp * 16 + lr) * 68 + ks * 8 + lc];
            unsigned af[4] = {ab[0], ab[8 * 68], ab[4], ab[8 * 68 + 4]};
#pragma unroll
            for (int nt = 0; nt < 2; nt++) {
                const unsigned* bp = &smU[SK + (nq * 16 + nt * 8 + lr) * 68 + ks * 8 + lc];
                unsigned bf[2] = {bp[0], bp[4]};
                mma8(acc[nt], af, bf);
            }
        }
#pragma unroll
        for (int nt = 0; nt < 2; nt++) {
            int c0 = nq * 16 + nt * 8 + 2 * lc;
            int r = mtp * 16 + lr;
            float b0 = __ldg(&pb[c0]), b1 = __ldg(&pb[c0 + 1]);
            *(float2*)&out[((size_t)b * NN + n0 + r) * 64 + c0] =
                make_float2(acc[nt][0] + b0, acc[nt][1] + b1);
            *(float2*)&out[((size_t)b * NN + n0 + r + 8) * 64 + c0] =
                make_float2(acc[nt][2] + b0, acc[nt][3] + b1);
        }
    }
}

// ---------------- launch ----------------
extern "C" void kernel_launch(void* const* d_in, const int* in_sizes, int n_in,
                              void* d_out, int out_size) {
    const float* x     = (const float*)d_in[0];
    const float* pos   = (const float*)d_in[1];
    const float* qw    = (const float*)d_in[2];
    const float* qb    = (const float*)d_in[3];
    const float* kvw   = (const float*)d_in[4];
    const float* kvb   = (const float*)d_in[5];
    const float* pw    = (const float*)d_in[6];
    const float* pb    = (const float*)d_in[7];
    const float* srw   = (const float*)d_in[8];
    const float* srb   = (const float*)d_in[9];
    const float* lng   = (const float*)d_in[10];
    const float* lnb   = (const float*)d_in[11];
    const float* alpha = (const float*)d_in[12];
    float* out = (float*)d_out;

    cudaFuncSetAttribute(k_attn, cudaFuncAttributeMaxDynamicSharedMemorySize,
                         SMFW * 4);

    k_transpose<<<256, 256>>>(srw);
    k_conv<<<dim3(16, 16), 256>>>(x);
    k_lnkv<<<512, 256>>>(srb, lng, lnb, kvw, kvb);
    k_attn<<<dim3(256, 4), 512, SMFW * 4>>>(x, pos, qw, qb, pw, pb, alpha, out);
}

// round 12
// speedup vs baseline: 4.3692x; 1.0148x over previous
#include <cuda_runtime.h>
#include <math.h>

// Problem constants
#define BB   4
#define NN   16384
#define QK_SCALE 0.17677669529663687f   // 32^-0.5

// ---------------- scratch (device globals; no allocation) ----------------
__device__ float    g_wt[64 * 4096];         // conv weights transposed [o][k]
__device__ float    g_part[16 * 1024 * 64];  // conv split-K partials
__device__ unsigned g_ktf[8 * 256 * 32];     // K tf32 [b*2+h][m][d]
__device__ unsigned g_vhi[8 * 128 * 32];     // V bf16-hi pairs [b*2+h][k2][n]
__device__ unsigned g_vlo[8 * 128 * 32];     // V bf16-lo pairs [b*2+h][k2][n]

// ---------------- helpers ----------------
__device__ __forceinline__ unsigned f2tf(float f) {
    unsigned u; asm("cvt.rna.tf32.f32 %0, %1;" : "=r"(u) : "f"(f)); return u;
}
__device__ __forceinline__ unsigned packbf(float lo, float hi) {
    unsigned u; asm("cvt.rn.bf16x2.f32 %0, %1, %2;" : "=r"(u) : "f"(hi), "f"(lo)); return u;
}
__device__ __forceinline__ float bf_lo(unsigned u) { return __uint_as_float(u << 16); }
__device__ __forceinline__ float bf_hi(unsigned u) { return __uint_as_float(u & 0xffff0000u); }
__device__ __forceinline__ void mma8(float d[4], const unsigned a[4], const unsigned b[2]) {
    asm volatile(
        "mma.sync.aligned.m16n8k8.row.col.f32.tf32.tf32.f32 "
        "{%0,%1,%2,%3},{%4,%5,%6,%7},{%8,%9},{%0,%1,%2,%3};"
        : "+f"(d[0]), "+f"(d[1]), "+f"(d[2]), "+f"(d[3])
        : "r"(a[0]), "r"(a[1]), "r"(a[2]), "r"(a[3]), "r"(b[0]), "r"(b[1]));
}
__device__ __forceinline__ void mma16b(float d[4], const unsigned a[4], const unsigned b[2]) {
    asm volatile(
        "mma.sync.aligned.m16n8k16.row.col.f32.bf16.bf16.f32 "
        "{%0,%1,%2,%3},{%4,%5,%6,%7},{%8,%9},{%0,%1,%2,%3};"
        : "+f"(d[0]), "+f"(d[1]), "+f"(d[2]), "+f"(d[3])
        : "r"(a[0]), "r"(a[1]), "r"(a[2]), "r"(a[3]), "r"(b[0]), "r"(b[1]));
}
__device__ __forceinline__ void cpa16(unsigned dst, const void* src) {
    asm volatile("cp.async.cg.shared.global [%0], [%1], 16;" :: "r"(dst), "l"(src));
}
#define CP_COMMIT() asm volatile("cp.async.commit_group;")
#define CP_WAIT(n)  asm volatile("cp.async.wait_group %0;" :: "n"(n))
#define GROUP_BAR(id) asm volatile("bar.sync %0, 128;" :: "r"(id) : "memory")

// ---------------- kernel 0: weight transpose ----------------
__global__ void __launch_bounds__(256) k_transpose(const float* __restrict__ srw) {
    int base = blockIdx.x * 256 + threadIdx.x;
#pragma unroll
    for (int it = 0; it < 4; it++) {
        int i = base + it * 65536;
        int o   = i >> 12;
        int kg  = i & 4095;
        int tap = kg >> 6, c = kg & 63;
        int kh = tap >> 3, kw = tap & 7;
        g_wt[i] = srw[((o * 64 + c) * 8 + kh) * 8 + kw];
    }
}

// ---------------- kernel 1: SR conv, cp.async double-buffered tf32 mma ----------------
__global__ void __launch_bounds__(256) k_conv(const float* __restrict__ x) {
    __shared__ float As[2][1280];   // [stage][64*20] raw fp32
    __shared__ float Bsm[2][1280];
    unsigned smbA = (unsigned)__cvta_generic_to_shared(&As[0][0]);
    unsigned smbB = (unsigned)__cvta_generic_to_shared(&Bsm[0][0]);
    int tid = threadIdx.x, w = tid >> 5, ln = tid & 31;
    int lr = ln >> 2, lc = ln & 3;
    int mtile = blockIdx.x, ks = blockIdx.y;
    int mt = w & 3, nq = w >> 2;
    float acc[4][4] = {};

    int lm = tid >> 2, lkq = tid & 3;
    int gm = mtile * 64 + lm;
    int bb = gm >> 8, pos = gm & 255;
    int oh = pos >> 4, ow = pos & 15;

    // prefetch iteration 0
    {
        int kg = ks * 256 + lkq * 4;
        int tap = kg >> 6, c = kg & 63;
        int kh = tap >> 3, kw = tap & 7;
        int pix = (oh * 8 + kh) * 128 + (ow * 8 + kw);
        cpa16(smbA + (lm * 20 + lkq * 4) * 4, &x[(bb * NN + pix) * 64 + c]);
        cpa16(smbB + (lm * 20 + lkq * 4) * 4, &g_wt[lm * 4096 + ks * 256 + lkq * 4]);
        CP_COMMIT();
    }

    for (int i = 0; i < 16; i++) {
        if (i < 15) {
            int s = (i + 1) & 1;
            int kg = ks * 256 + (i + 1) * 16 + lkq * 4;
            int tap = kg >> 6, c = kg & 63;
            int kh = tap >> 3, kw = tap & 7;
            int pix = (oh * 8 + kh) * 128 + (ow * 8 + kw);
            cpa16(smbA + (s * 1280 + lm * 20 + lkq * 4) * 4, &x[(bb * NN + pix) * 64 + c]);
            cpa16(smbB + (s * 1280 + lm * 20 + lkq * 4) * 4,
                  &g_wt[lm * 4096 + ks * 256 + (i + 1) * 16 + lkq * 4]);
            CP_COMMIT();
            CP_WAIT(1);
        } else {
            CP_WAIT(0);
        }
        __syncthreads();
        const float* Ab = As[i & 1];
        const float* Bb = Bsm[i & 1];
#pragma unroll
        for (int kb = 0; kb < 16; kb += 8) {
            const float* ap = &Ab[(mt * 16 + lr) * 20 + kb + lc];
            unsigned af[4] = {f2tf(ap[0]), f2tf(ap[8 * 20]), f2tf(ap[4]), f2tf(ap[8 * 20 + 4])};
#pragma unroll
            for (int nt = 0; nt < 4; nt++) {
                const float* bp = &Bb[(nq * 32 + nt * 8 + lr) * 20 + kb + lc];
                unsigned bf[2] = {f2tf(bp[0]), f2tf(bp[4])};
                mma8(acc[nt], af, bf);
            }
        }
        __syncthreads();
    }
    float* outp = &g_part[ks * 65536 + (mtile * 64) * 64];
#pragma unroll
    for (int nt = 0; nt < 4; nt++) {
        int r = mt * 16 + lr, c0 = nq * 32 + nt * 8 + 2 * lc;
        *(float2*)&outp[r * 64 + c0]       = make_float2(acc[nt][0], acc[nt][1]);
        *(float2*)&outp[(r + 8) * 64 + c0] = make_float2(acc[nt][2], acc[nt][3]);
    }
}

// ---------------- kernel 2: reduce partials -> LN -> kv proj -> precomputed formats ----
__global__ void __launch_bounds__(256) k_lnkv(
    const float* __restrict__ srb, const float* __restrict__ lng,
    const float* __restrict__ lnb, const float* __restrict__ kvw,
    const float* __restrict__ kvb)
{
    __shared__ float snx[2][64];
    __shared__ float red[2][2][2];
    __shared__ float vsm[2][64];
    int tid = threadIdx.x, sub = tid >> 7, t = tid & 127;
    int m = blockIdx.x * 2 + sub;
    float v = 0.f;
    if (t < 64) {
        v = srb[t];
#pragma unroll
        for (int s = 0; s < 16; s++) v += g_part[s * 65536 + m * 64 + t];
        float sv = v, sq = v * v;
#pragma unroll
        for (int off = 16; off; off >>= 1) {
            sv += __shfl_xor_sync(0xffffffffu, sv, off);
            sq += __shfl_xor_sync(0xffffffffu, sq, off);
        }
        if ((t & 31) == 0) { red[sub][t >> 5][0] = sv; red[sub][t >> 5][1] = sq; }
    }
    __syncthreads();
    float mu  = (red[sub][0][0] + red[sub][1][0]) * (1.f / 64.f);
    float var = (red[sub][0][1] + red[sub][1][1]) * (1.f / 64.f) - mu * mu;
    float rstd = rsqrtf(var + 1e-5f);
    if (t < 64) snx[sub][t] = (v - mu) * rstd * lng[t] + lnb[t];
    __syncthreads();

    int o = t;
    float acc = kvb[o];
#pragma unroll
    for (int c4 = 0; c4 < 16; c4++) {
        float4 ww = *(const float4*)&kvw[o * 64 + c4 * 4];
        acc += snx[sub][c4 * 4 + 0] * ww.x + snx[sub][c4 * 4 + 1] * ww.y
             + snx[sub][c4 * 4 + 2] * ww.z + snx[sub][c4 * 4 + 3] * ww.w;
    }
    int bb = m >> 8, mm = m & 255;
    if (o < 64) {
        int h = o >> 5, d = o & 31;
        g_ktf[((bb * 2 + h) * 256 + mm) * 32 + d] = f2tf(acc);
    } else {
        vsm[sub][o - 64] = acc;
    }
    __syncthreads();
    if (tid < 64) {
        int h = tid >> 5, d = tid & 31;
        float v0 = vsm[0][tid], v1 = vsm[1][tid];
        unsigned hi = packbf(v0, v1);
        unsigned lo = packbf(v0 - bf_lo(hi), v1 - bf_hi(hi));
        int bb2 = blockIdx.x >> 7, k2 = blockIdx.x & 127;
        int idx = ((bb2 * 2 + h) * 128 + k2) * 32 + d;
        g_vhi[idx] = hi;
        g_vlo[idx] = lo;
    }
}

// ---------------- kernel 3: fused attention, full cp.async + named barriers ----------
// smem layout (4-byte words):
#define SQ    0        // q tf32 [r*68 + h*32+d], scale folded          (4352)
#define SOB   4352     // qw raw at start; attn-out tf32 [r*68+c]       (4352)
#define SK    8704     // K tf32 head [m*36+d]; pw raw [o*68+c] at end  (9216)
#define SVH   17920    // V bf16-hi packed [k2*40 + n]                  (5120)
#define SVL   23040    // V bf16-lo packed [k2*40 + n]                  (5120)
#define SRED  28160    // x-tile raw at start; attn@V partials [nh][64][34] (8704)
#define SROW  36864    // row sums [64][4]                              (256)
#define SPOS  37120    // pos tile f32 [64][260]                        (16640)
#define SMFW  53760    // words -> 215040 bytes

__global__ void __launch_bounds__(512, 1) k_attn(
    const float* __restrict__ x,  const float* __restrict__ pos,
    const float* __restrict__ qw, const float* __restrict__ qb,
    const float* __restrict__ pw, const float* __restrict__ pb,
    const float* __restrict__ alpha, float* __restrict__ out)
{
    extern __shared__ float sm[];
    unsigned* smU = (unsigned*)sm;
    unsigned smb = (unsigned)__cvta_generic_to_shared(sm);
    int tid = threadIdx.x, w = tid >> 5, ln = tid & 31;
    int lr = ln >> 2, lc = ln & 3;
    int b = blockIdx.y;
    int n0 = blockIdx.x * 64;
    float a_ = __ldg(alpha);

    int mt = w & 3, nh = w >> 2;            // logits/attn decomposition
    int rowA = mt * 16 + lr;

    // ---- G0: x tile raw -> SRED, qw raw -> SOB ----
#pragma unroll
    for (int it = 0; it < 2; it++) {
        int lin = it * 512 + tid;
        int r = lin >> 4, c4 = (lin & 15) * 4;
        cpa16(smb + (SRED + r * 68 + c4) * 4, &x[((size_t)b * NN + n0 + r) * 64 + c4]);
        cpa16(smb + (SOB + r * 68 + c4) * 4, &qw[r * 64 + c4]);
    }
    CP_COMMIT();
    // ---- G1: K0 + V0 ----
    {
        int b2h = b * 2;
#pragma unroll
        for (int it = 0; it < 4; it++) {
            int lin = it * 512 + tid;
            int m = lin >> 3, d4 = (lin & 7) * 4;
            cpa16(smb + (SK + m * 36 + d4) * 4, &g_ktf[(b2h * 256 + m) * 32 + d4]);
        }
#pragma unroll
        for (int it = 0; it < 2; it++) {
            int lin = it * 512 + tid;
            int k2 = lin >> 3, n4 = (lin & 7) * 4;
            cpa16(smb + (SVH + k2 * 40 + n4) * 4, &g_vhi[(b2h * 128 + k2) * 32 + n4]);
            cpa16(smb + (SVL + k2 * 40 + n4) * 4, &g_vlo[(b2h * 128 + k2) * 32 + n4]);
        }
        CP_COMMIT();
    }
    // ---- G2: pos0 slice (warp-private 16x64) ----
    {
        int b2h = b * 2;
#pragma unroll
        for (int i = 0; i < 8; i++) {
            int q = ln + 32 * i;
            int r = q >> 4, ch = q & 15;
            cpa16(smb + (SPOS + (mt * 16 + r) * 260 + nh * 64 + ch * 4) * 4,
                  &pos[((size_t)b2h * NN + n0 + mt * 16 + r) * 256 + nh * 64 + ch * 4]);
        }
        CP_COMMIT();
    }

    CP_WAIT(2);          // G0 complete (G1,G2 pending)
    __syncthreads();     // B1

    // ---- q-proj: SQ = x @ qw^T (cvt at use, scale folded) ----
    {
        int mtp = w >> 2, nq = w & 3;
        float acc[2][4] = {};
#pragma unroll
        for (int ks = 0; ks < 8; ks++) {
            const float* ap = &sm[SRED + (mtp * 16 + lr) * 68 + ks * 8 + lc];
            unsigned af[4] = {f2tf(ap[0]), f2tf(ap[8 * 68]), f2tf(ap[4]), f2tf(ap[8 * 68 + 4])};
#pragma unroll
            for (int nt = 0; nt < 2; nt++) {
                const float* bp = &sm[SOB + (nq * 16 + nt * 8 + lr) * 68 + ks * 8 + lc];
                unsigned bf[2] = {f2tf(bp[0]), f2tf(bp[4])};
                mma8(acc[nt], af, bf);
            }
        }
#pragma unroll
        for (int nt = 0; nt < 2; nt++) {
            int c0 = nq * 16 + nt * 8 + 2 * lc;
            int r = mtp * 16 + lr;
            float b0 = __ldg(&qb[c0]), b1 = __ldg(&qb[c0 + 1]);
            smU[SQ + r * 68 + c0]           = f2tf((acc[nt][0] + b0) * QK_SCALE);
            smU[SQ + r * 68 + c0 + 1]       = f2tf((acc[nt][1] + b1) * QK_SCALE);
            smU[SQ + (r + 8) * 68 + c0]     = f2tf((acc[nt][2] + b0) * QK_SCALE);
            smU[SQ + (r + 8) * 68 + c0 + 1] = f2tf((acc[nt][3] + b1) * QK_SCALE);
        }
    }
    CP_WAIT(1);          // G1 (K0/V0) complete (G2 pending)
    __syncthreads();     // B2

    for (int h = 0; h < 2; h++) {
        int b2h = b * 2 + h;

        // ---- logits rows [mt*16..+15], cols [nh*64..+63] (registers) ----
        float acc[8][4];
#pragma unroll
        for (int i = 0; i < 8; i++)
            acc[i][0] = acc[i][1] = acc[i][2] = acc[i][3] = 0.f;
#pragma unroll
        for (int ks = 0; ks < 4; ks++) {
            const unsigned* ab = &smU[SQ + rowA * 68 + h * 32 + ks * 8 + lc];
            unsigned af[4] = {ab[0], ab[8 * 68], ab[4], ab[8 * 68 + 4]};
#pragma unroll
            for (int nt = 0; nt < 8; nt++) {
                const unsigned* bp = &smU[SK + (nh * 64 + nt * 8 + lr) * 36 + ks * 8 + lc];
                unsigned bf[2] = {bp[0], bp[4]};
                mma8(acc[nt], af, bf);
            }
        }

        // ---- exp + row sums; exchange within mt-group only ----
        float s0 = 0.f, s1 = 0.f;
#pragma unroll
        for (int nt = 0; nt < 8; nt++) {
            acc[nt][0] = __expf(acc[nt][0]); s0 += acc[nt][0];
            acc[nt][1] = __expf(acc[nt][1]); s0 += acc[nt][1];
            acc[nt][2] = __expf(acc[nt][2]); s1 += acc[nt][2];
            acc[nt][3] = __expf(acc[nt][3]); s1 += acc[nt][3];
        }
        s0 += __shfl_xor_sync(0xffffffffu, s0, 1);
        s0 += __shfl_xor_sync(0xffffffffu, s0, 2);
        s1 += __shfl_xor_sync(0xffffffffu, s1, 1);
        s1 += __shfl_xor_sync(0xffffffffu, s1, 2);
        if (lc == 0) {
            sm[SROW + rowA * 4 + nh]       = s0;
            sm[SROW + (rowA + 8) * 4 + nh] = s1;
        }
        GROUP_BAR(mt + 1);     // only the 4 warps sharing mt need the sums

        float4 s40 = *(float4*)&sm[SROW + rowA * 4];
        float4 s41 = *(float4*)&sm[SROW + (rowA + 8) * 4];
        float inv0 = (1.f - a_) / (s40.x + s40.y + s40.z + s40.w);
        float inv1 = (1.f - a_) / (s41.x + s41.y + s41.z + s41.w);

        if (h == 0) {          // pos0 (G2) — warp-local wait
            CP_WAIT(0);
            __syncwarp();
        }

        // ---- blend (pos from smem) + split-bf16 pack + attn@V partial ----
        float accO[4][4];
#pragma unroll
        for (int i = 0; i < 4; i++)
            accO[i][0] = accO[i][1] = accO[i][2] = accO[i][3] = 0.f;
#pragma unroll
        for (int kk = 0; kk < 4; kk++) {
            unsigned afh[4], afl[4];
#pragma unroll
            for (int q = 0; q < 2; q++) {
                int nt = 2 * kk + q;
                int cb = nh * 64 + nt * 8 + 2 * lc;
                float2 p0 = *(const float2*)&sm[SPOS + rowA * 260 + cb];
                float2 p1 = *(const float2*)&sm[SPOS + (rowA + 8) * 260 + cb];
                float w00 = acc[nt][0] * inv0 + a_ * p0.x;
                float w01 = acc[nt][1] * inv0 + a_ * p0.y;
                float w10 = acc[nt][2] * inv1 + a_ * p1.x;
                float w11 = acc[nt][3] * inv1 + a_ * p1.y;
                unsigned h0 = packbf(w00, w01);
                unsigned h1 = packbf(w10, w11);
                afh[2 * q]     = h0;
                afh[2 * q + 1] = h1;
                afl[2 * q]     = packbf(w00 - bf_lo(h0), w01 - bf_hi(h0));
                afl[2 * q + 1] = packbf(w10 - bf_lo(h1), w11 - bf_hi(h1));
            }
            int k2b = nh * 32 + kk * 8;
#pragma unroll
            for (int ntv = 0; ntv < 4; ntv++) {
                const unsigned* bph = &smU[SVH + (k2b + lc) * 40 + ntv * 8 + lr];
                const unsigned* bpl = &smU[SVL + (k2b + lc) * 40 + ntv * 8 + lr];
                unsigned bh[2] = {bph[0], bph[4 * 40]};
                unsigned bl[2] = {bpl[0], bpl[4 * 40]};
                mma16b(accO[ntv], afh, bh);
                mma16b(accO[ntv], afh, bl);
                mma16b(accO[ntv], afl, bh);
            }
        }

        if (h == 0) {          // G4: pos1 slice (own slice read done; warp-private)
#pragma unroll
            for (int i = 0; i < 8; i++) {
                int q = ln + 32 * i;
                int r = q >> 4, ch = q & 15;
                cpa16(smb + (SPOS + (mt * 16 + r) * 260 + nh * 64 + ch * 4) * 4,
                      &pos[((size_t)(b2h + 1) * NN + n0 + mt * 16 + r) * 256 + nh * 64 + ch * 4]);
            }
            CP_COMMIT();
        }

        // write partials [nh][row][col]
#pragma unroll
        for (int ntv = 0; ntv < 4; ntv++) {
            int cc = ntv * 8 + 2 * lc;
            *(float2*)&sm[SRED + nh * 2176 + rowA * 34 + cc] =
                make_float2(accO[ntv][0], accO[ntv][1]);
            *(float2*)&sm[SRED + nh * 2176 + (rowA + 8) * 34 + cc] =
                make_float2(accO[ntv][2], accO[ntv][3]);
        }
        __syncthreads();       // B3 full: partials visible; all SK/SV reads done

        if (h == 0) {          // G35: K1 + V1 (after ALL logits/attn@V reads)
#pragma unroll
            for (int it = 0; it < 4; it++) {
                int lin = it * 512 + tid;
                int m = lin >> 3, d4 = (lin & 7) * 4;
                cpa16(smb + (SK + m * 36 + d4) * 4,
                      &g_ktf[((b2h + 1) * 256 + m) * 32 + d4]);
            }
#pragma unroll
            for (int it = 0; it < 2; it++) {
                int lin = it * 512 + tid;
                int k2 = lin >> 3, n4 = (lin & 7) * 4;
                cpa16(smb + (SVH + k2 * 40 + n4) * 4,
                      &g_vhi[((b2h + 1) * 128 + k2) * 32 + n4]);
                cpa16(smb + (SVL + k2 * 40 + n4) * 4,
                      &g_vlo[((b2h + 1) * 128 + k2) * 32 + n4]);
            }
            CP_COMMIT();
        } else {               // G6: pw raw -> SK (K reads all done)
#pragma unroll
            for (int it = 0; it < 2; it++) {
                int lin = it * 512 + tid;
                int r = lin >> 4, c4 = (lin & 15) * 4;
                cpa16(smb + (SK + r * 68 + c4) * 4, &pw[r * 64 + c4]);
            }
            CP_COMMIT();
        }

        // ---- reduce own-group rows: partials -> SOB (tf32) ----
        {
            int tg = (w >> 2) * 32 + ln;      // 0..127 within mt-group
#pragma unroll
            for (int i = 0; i < 2; i++) {
                int p = i * 128 + tg;         // 0..255
                int r = mt * 16 + (p >> 4);
                int c2 = (p & 15) * 2;
                float sx = 0.f, sy = 0.f;
#pragma unroll
                for (int g = 0; g < 4; g++) {
                    float2 t = *(float2*)&sm[SRED + g * 2176 + r * 34 + c2];
                    sx += t.x; sy += t.y;
                }
                smU[SOB + r * 68 + h * 32 + c2]     = f2tf(sx);
                smU[SOB + r * 68 + h * 32 + c2 + 1] = f2tf(sy);
            }
        }
        CP_WAIT(0);            // drain pending (h0: G4+G35, h1: G6)
        __syncthreads();       // B4 full: SOB + freshly staged data visible
    }

    // ---- out-proj: out = attn_out @ pw^T + pb (pw raw in SK, cvt at use) ----
    {
        int mtp = w >> 2, nq = w & 3;
        float acc[2][4] = {};
#pragma unroll
        for (int ks = 0; ks < 8; ks++) {
            const unsigned* ab = &smU[SOB + (mtp * 16 + lr) * 68 + ks * 8 + lc];
            unsigned af[4] = {ab[0], ab[8 * 68], ab[4], ab[8 * 68 + 4]};
#pragma unroll
            for (int nt = 0; nt < 2; nt++) {
                const float* bp = &sm[SK + (nq * 16 + nt * 8 + lr) * 68 + ks * 8 + lc];
                unsigned bf[2] = {f2tf(bp[0]), f2tf(bp[4])};
                mma8(acc[nt], af, bf);
            }
        }
#pragma unroll
        for (int nt = 0; nt < 2; nt++) {
            int c0 = nq * 16 + nt * 8 + 2 * lc;
            int r = mtp * 16 + lr;
            float b0 = __ldg(&pb[c0]), b1 = __ldg(&pb[c0 + 1]);
            *(float2*)&out[((size_t)b * NN + n0 + r) * 64 + c0] =
                make_float2(acc[nt][0] + b0, acc[nt][1] + b1);
            *(float2*)&out[((size_t)b * NN + n0 + r + 8) * 64 + c0] =
                make_float2(acc[nt][2] + b0, acc[nt][3] + b1);
        }
    }
}

// ---------------- launch ----------------
extern "C" void kernel_launch(void* const* d_in, const int* in_sizes, int n_in,
                              void* d_out, int out_size) {
    const float* x     = (const float*)d_in[0];
    const float* pos   = (const float*)d_in[1];
    const float* qw    = (const float*)d_in[2];
    const float* qb    = (const float*)d_in[3];
    const float* kvw   = (const float*)d_in[4];
    const float* kvb   = (const float*)d_in[5];
    const float* pw    = (const float*)d_in[6];
    const float* pb    = (const float*)d_in[7];
    const float* srw   = (const float*)d_in[8];
    const float* srb   = (const float*)d_in[9];
    const float* lng   = (const float*)d_in[10];
    const float* lnb   = (const float*)d_in[11];
    const float* alpha = (const float*)d_in[12];
    float* out = (float*)d_out;

    cudaFuncSetAttribute(k_attn, cudaFuncAttributeMaxDynamicSharedMemorySize,
                         SMFW * 4);

    k_transpose<<<256, 256>>>(srw);
    k_conv<<<dim3(16, 16), 256>>>(x);
    k_lnkv<<<512, 256>>>(srb, lng, lnb, kvw, kvb);
    k_attn<<<dim3(256, 4), 512, SMFW * 4>>>(x, pos, qw, qb, pw, pb, alpha, out);
}